// round 2
// baseline (speedup 1.0000x reference)
#include <cuda_runtime.h>
#include <math.h>

// Problem dims (fixed by the reference)
// B=4096, T=8, CH_IN=2048, C=1024, N=512, K=5, EPS=1e-8
// All GEMM dims are multiples of 128 -> no edge handling needed.

__device__ float g_k  [4096u * 1024u];          // k, then kn (in place)
__device__ float g_v  [4096u * 1024u];          // v
__device__ float g_Ek [5u * 1024u * 512u];      // Ek, then Ekn (in place)
__device__ float g_Ev [5u * 1024u * 512u];      // Ev
__device__ float g_sim[4096u * 5u * 512u];      // sim, then softmax w (in place)
__device__ float g_fe [5u * 4096u * 1024u];     // feature_E laid out [k][b][c]

// ---------------------------------------------------------------------------
// Generic 128x128x8 fp32 tiled GEMM, 256 threads, 8x8 microtile.
// TB=0: C[m,n] = sum_k A[m,k] * B[k,n]   (NN)
// TB=1: C[m,n] = sum_k A[m,k] * B[n,k]   (NT)
// Optional bias along rows (bias_m) and/or cols (bias_n).
// blockIdx.z batches with the given element strides.
// ---------------------------------------------------------------------------
template <int TB>
__global__ __launch_bounds__(256)
void gemm_tile(const float* __restrict__ A, long lda, long sAz,
               const float* __restrict__ Bm, long ldb, long sBz,
               float* __restrict__ Cm, long ldc, long sCz,
               int Kd,
               const float* __restrict__ bias_m,
               const float* __restrict__ bias_n)
{
    A  += (long)blockIdx.z * sAz;
    Bm += (long)blockIdx.z * sBz;
    Cm += (long)blockIdx.z * sCz;
    const int m0 = blockIdx.y * 128;
    const int n0 = blockIdx.x * 128;
    const int tid = threadIdx.x;

    __shared__ float As[8][128];
    __shared__ float Bs[8][128];

    const int tx = tid & 15;        // col group
    const int ty = tid >> 4;        // row group

    float acc[8][8];
#pragma unroll
    for (int i = 0; i < 8; i++)
#pragma unroll
        for (int j = 0; j < 8; j++) acc[i][j] = 0.f;

    // load index helpers
    const int arow = tid >> 1;            // 0..127
    const int ac   = (tid & 1) * 4;       // 0 or 4
    const int brow = tid >> 5;            // 0..7   (NN B load)
    const int bcol = (tid & 31) * 4;      // 0..124 (NN B load)

    for (int kt = 0; kt < Kd; kt += 8) {
        // prefetch to registers (overlaps with previous tile's compute)
        float4 av = *(const float4*)(A + (long)(m0 + arow) * lda + kt + ac);
        float4 bv;
        if (TB) bv = *(const float4*)(Bm + (long)(n0 + arow) * ldb + kt + ac);
        else    bv = *(const float4*)(Bm + (long)(kt + brow) * ldb + n0 + bcol);

        __syncthreads();
        As[ac + 0][arow] = av.x; As[ac + 1][arow] = av.y;
        As[ac + 2][arow] = av.z; As[ac + 3][arow] = av.w;
        if (TB) {
            Bs[ac + 0][arow] = bv.x; Bs[ac + 1][arow] = bv.y;
            Bs[ac + 2][arow] = bv.z; Bs[ac + 3][arow] = bv.w;
        } else {
            *(float4*)&Bs[brow][bcol] = bv;
        }
        __syncthreads();

#pragma unroll
        for (int kk = 0; kk < 8; kk++) {
            float4 a0 = *(const float4*)&As[kk][ty * 4];
            float4 a1 = *(const float4*)&As[kk][64 + ty * 4];
            float4 b0 = *(const float4*)&Bs[kk][tx * 4];
            float4 b1 = *(const float4*)&Bs[kk][64 + tx * 4];
            float ar[8] = {a0.x, a0.y, a0.z, a0.w, a1.x, a1.y, a1.z, a1.w};
            float br[8] = {b0.x, b0.y, b0.z, b0.w, b1.x, b1.y, b1.z, b1.w};
#pragma unroll
            for (int i = 0; i < 8; i++)
#pragma unroll
                for (int j = 0; j < 8; j++)
                    acc[i][j] = fmaf(ar[i], br[j], acc[i][j]);
        }
    }

    // epilogue
    float bn[8];
#pragma unroll
    for (int j = 0; j < 8; j++) {
        int gc = n0 + ((j < 4) ? tx * 4 + j : 64 + tx * 4 + (j - 4));
        bn[j] = bias_n ? bias_n[gc] : 0.f;
    }
#pragma unroll
    for (int i = 0; i < 8; i++) {
        int gr = m0 + ((i < 4) ? ty * 4 + i : 64 + ty * 4 + (i - 4));
        float bm = bias_m ? bias_m[gr] : 0.f;
        float4 o0 = make_float4(acc[i][0] + bm + bn[0], acc[i][1] + bm + bn[1],
                                acc[i][2] + bm + bn[2], acc[i][3] + bm + bn[3]);
        float4 o1 = make_float4(acc[i][4] + bm + bn[4], acc[i][5] + bm + bn[5],
                                acc[i][6] + bm + bn[6], acc[i][7] + bm + bn[7]);
        *(float4*)(Cm + (long)gr * ldc + n0 + tx * 4)      = o0;
        *(float4*)(Cm + (long)gr * ldc + n0 + 64 + tx * 4) = o1;
    }
}

// Normalize Ek columns over c: Ekn[k,:,n] = Ek[k,:,n] / max(||.||, eps).
// One thread per (k, n); E layout [k][c][n], stride over c is 512.
__global__ void norm_cols_kernel(float* __restrict__ E)
{
    int idx = blockIdx.x * blockDim.x + threadIdx.x;   // 0..2559
    int kk = idx >> 9, n = idx & 511;
    float* base = E + (long)kk * (1024 * 512) + n;
    float s = 0.f;
#pragma unroll 4
    for (int c = 0; c < 1024; c++) { float v = base[(long)c * 512]; s = fmaf(v, v, s); }
    float inv = 1.f / fmaxf(sqrtf(s), 1e-8f);
#pragma unroll 4
    for (int c = 0; c < 1024; c++) base[(long)c * 512] *= inv;
}

// Normalize k rows over c (1024 elems), in place. grid = B, 256 threads.
__global__ void norm_rows_kernel(float* __restrict__ Kb)
{
    int b = blockIdx.x, tid = threadIdx.x;
    float* row = Kb + (long)b * 1024;
    float4 v = *(float4*)&row[tid * 4];
    __shared__ float sred[256];
    sred[tid] = v.x * v.x + v.y * v.y + v.z * v.z + v.w * v.w;
    __syncthreads();
    for (int st = 128; st > 0; st >>= 1) {
        if (tid < st) sred[tid] += sred[tid + st];
        __syncthreads();
    }
    float inv = 1.f / fmaxf(sqrtf(sred[0]), 1e-8f);
    v.x *= inv; v.y *= inv; v.z *= inv; v.w *= inv;
    *(float4*)&row[tid * 4] = v;
}

// Softmax over the last 512 elems; grid = B*K, 128 threads, in place.
__global__ void softmax_kernel(float* __restrict__ S)
{
    float* base = S + (long)blockIdx.x * 512;
    int tid = threadIdx.x;
    float4 v = *(float4*)&base[tid * 4];
    __shared__ float sred[128];
    sred[tid] = fmaxf(fmaxf(v.x, v.y), fmaxf(v.z, v.w));
    __syncthreads();
    for (int st = 64; st > 0; st >>= 1) {
        if (tid < st) sred[tid] = fmaxf(sred[tid], sred[tid + st]);
        __syncthreads();
    }
    float m = sred[0];
    __syncthreads();
    v.x = expf(v.x - m); v.y = expf(v.y - m); v.z = expf(v.z - m); v.w = expf(v.w - m);
    sred[tid] = v.x + v.y + v.z + v.w;
    __syncthreads();
    for (int st = 64; st > 0; st >>= 1) {
        if (tid < st) sred[tid] += sred[tid + st];
        __syncthreads();
    }
    float inv = 1.f / sred[0];
    v.x *= inv; v.y *= inv; v.z *= inv; v.w *= inv;
    *(float4*)&base[tid * 4] = v;
}

// Gate + concat + output GEMV per batch row. grid = B, 256 threads.
// fe layout: [k][b][c].
__global__ void final_kernel(const float* __restrict__ vbuf,
                             const float* __restrict__ fe,
                             const float* __restrict__ Ww,
                             const float* __restrict__ bw,
                             const float* __restrict__ Wout,
                             const float* __restrict__ bout,
                             float* __restrict__ out)
{
    const int b = blockIdx.x, tid = threadIdx.x;
    const long bc = (long)b * 1024;
    const long sz = (long)4096 * 1024;
    __shared__ float sred[256];
    __shared__ float s_fw[5];

    // fw[k] = sigmoid(sum_c Ww[c] * fe[k][b][c] + bw)
    float acc[5] = {0.f, 0.f, 0.f, 0.f, 0.f};
    for (int c = tid; c < 1024; c += 256) {
        float wv = Ww[c];
#pragma unroll
        for (int kk = 0; kk < 5; kk++)
            acc[kk] = fmaf(wv, fe[sz * kk + bc + c], acc[kk]);
    }
#pragma unroll
    for (int kk = 0; kk < 5; kk++) {
        __syncthreads();
        sred[tid] = acc[kk];
        __syncthreads();
        for (int st = 128; st > 0; st >>= 1) {
            if (tid < st) sred[tid] += sred[tid + st];
            __syncthreads();
        }
        if (tid == 0) s_fw[kk] = 1.f / (1.f + expf(-(sred[0] + bw[0])));
    }
    __syncthreads();
    float fwl[5];
#pragma unroll
    for (int kk = 0; kk < 5; kk++) fwl[kk] = s_fw[kk];

    // out[b][k2] = sum_j relu(h[j]) * Wout[k2][j] + bout[k2],
    // h = [v(1024) | fE(1024)], fE[c] = sum_k fe[k][b][c]*fw[k]
    float oacc[5] = {0.f, 0.f, 0.f, 0.f, 0.f};
    for (int j = tid; j < 2048; j += 256) {
        float h;
        if (j < 1024) {
            h = vbuf[bc + j];
        } else {
            int c = j - 1024;
            float s = 0.f;
#pragma unroll
            for (int kk = 0; kk < 5; kk++)
                s = fmaf(fe[sz * kk + bc + c], fwl[kk], s);
            h = s;
        }
        h = fmaxf(h, 0.f);
#pragma unroll
        for (int kk = 0; kk < 5; kk++)
            oacc[kk] = fmaf(h, Wout[kk * 2048 + j], oacc[kk]);
    }
#pragma unroll
    for (int kk = 0; kk < 5; kk++) {
        __syncthreads();
        sred[tid] = oacc[kk];
        __syncthreads();
        for (int st = 128; st > 0; st >>= 1) {
            if (tid < st) sred[tid] += sred[tid + st];
            __syncthreads();
        }
        if (tid == 0) out[b * 5 + kk] = sred[0] + bout[kk];
    }
}

extern "C" void kernel_launch(void* const* d_in, const int* in_sizes, int n_in,
                              void* d_out, int out_size)
{
    const float* x    = (const float*)d_in[0];   // (4096, 8, 2048)
    const float* stat = (const float*)d_in[1];   // (5, 2048, 512)
    const float* Wk   = (const float*)d_in[2];   // (1024, 2048)
    const float* bk   = (const float*)d_in[3];
    const float* Wv   = (const float*)d_in[4];
    const float* bv   = (const float*)d_in[5];
    const float* WEk  = (const float*)d_in[6];
    const float* bEk  = (const float*)d_in[7];
    const float* WEv  = (const float*)d_in[8];
    const float* bEv  = (const float*)d_in[9];
    const float* Ww   = (const float*)d_in[10];  // (1, 1024)
    const float* bw   = (const float*)d_in[11];  // (1,)
    const float* Wout = (const float*)d_in[12];  // (5, 2048)
    const float* bout = (const float*)d_in[13];  // (5,)
    float* out = (float*)d_out;                  // (4096, 5, 1)

    float *k_, *v_, *Ek_, *Ev_, *sim_, *fe_;
    cudaGetSymbolAddress((void**)&k_,   g_k);
    cudaGetSymbolAddress((void**)&v_,   g_v);
    cudaGetSymbolAddress((void**)&Ek_,  g_Ek);
    cudaGetSymbolAddress((void**)&Ev_,  g_Ev);
    cudaGetSymbolAddress((void**)&sim_, g_sim);
    cudaGetSymbolAddress((void**)&fe_,  g_fe);

    // k = x_last @ Wk^T + bk ; v = x_last @ Wv^T + bv   (NT, M=4096 N=1024 K=2048)
    gemm_tile<1><<<dim3(8, 32, 1), 256>>>(x + 7 * 2048, 8 * 2048, 0,
                                          Wk, 2048, 0, k_, 1024, 0, 2048, nullptr, bk);
    gemm_tile<1><<<dim3(8, 32, 1), 256>>>(x + 7 * 2048, 8 * 2048, 0,
                                          Wv, 2048, 0, v_, 1024, 0, 2048, nullptr, bv);

    // Ek[z] = WEk @ static[z] + bEk (row bias); Ev likewise (NN, M=1024 N=512 K=2048, z=5)
    gemm_tile<0><<<dim3(4, 8, 5), 256>>>(WEk, 2048, 0,
                                         stat, 512, (long)2048 * 512,
                                         Ek_, 512, (long)1024 * 512, 2048, bEk, nullptr);
    gemm_tile<0><<<dim3(4, 8, 5), 256>>>(WEv, 2048, 0,
                                         stat, 512, (long)2048 * 512,
                                         Ev_, 512, (long)1024 * 512, 2048, bEv, nullptr);

    norm_cols_kernel<<<(5 * 512) / 128, 128>>>(Ek_);   // Ek -> Ekn in place
    norm_rows_kernel<<<4096, 256>>>(k_);               // k  -> kn  in place

    // sim[b][z][n] = kn @ Ekn[z]  (NN, M=4096 N=512 K=1024, z=5), C row stride 2560
    gemm_tile<0><<<dim3(4, 32, 5), 256>>>(k_, 1024, 0,
                                          Ek_, 512, (long)1024 * 512,
                                          sim_, 5 * 512, 512, 1024, nullptr, nullptr);

    softmax_kernel<<<4096 * 5, 128>>>(sim_);           // sim -> w in place

    // fe[z][b][c] = w[:,z,:] @ Ev[z]^T (NT, M=4096 N=1024 K=512, z=5)
    gemm_tile<1><<<dim3(8, 32, 5), 256>>>(sim_, 5 * 512, 512,
                                          Ev_, 512, (long)1024 * 512,
                                          fe_, 1024, (long)4096 * 1024, 512, nullptr, nullptr);

    final_kernel<<<4096, 256>>>(v_, fe_, Ww, bw, Wout, bout, out);
}

// round 3
// speedup vs baseline: 2.3201x; 2.3201x over previous
#include <cuda_runtime.h>
#include <math.h>

// Problem dims (fixed): B=4096, T=8, CH_IN=2048, C=1024, N=512, K=5, EPS=1e-8
// All GEMM dims are multiples of 128.

__device__ float g_k  [4096u * 1024u];          // k, then kn (in place)
__device__ float g_v  [4096u * 1024u];          // v
__device__ float g_Ek [5u * 1024u * 512u];      // Ek, then Ekn (in place)
__device__ float g_Ev [5u * 1024u * 512u];      // Ev
__device__ float g_sim[4096u * 5u * 512u];      // sim, then softmax w (in place)
__device__ float g_fe [5u * 4096u * 1024u];     // feature_E laid out [k][b][c]

#define DINLINE __device__ __forceinline__

// Round fp32 -> tf32 (round to nearest). Keeping RN (not truncation) kills the
// coherent mantissa-truncation bias that would accumulate over K=2048.
DINLINE unsigned f2tf32(float f) {
    unsigned u;
    asm("cvt.rna.tf32.f32 %0, %1;" : "=r"(u) : "f"(f));
    return u;
}

DINLINE void mma_tf32(float* c, const unsigned* a, const unsigned* b) {
    asm volatile(
        "mma.sync.aligned.m16n8k8.row.col.f32.tf32.tf32.f32 "
        "{%0,%1,%2,%3}, {%4,%5,%6,%7}, {%8,%9}, {%0,%1,%2,%3};"
        : "+f"(c[0]), "+f"(c[1]), "+f"(c[2]), "+f"(c[3])
        : "r"(a[0]), "r"(a[1]), "r"(a[2]), "r"(a[3]),
          "r"(b[0]), "r"(b[1]));
}

// ---------------------------------------------------------------------------
// Tensor-core TF32 GEMM: 128x128x32 block tile, 256 threads (2x4 warps),
// each warp 64x32 via m16n8k8 fragments (4 m-tiles x 4 n-tiles).
// TB=0: C[m,n] = sum_k A[m,k] * B[k,n]   (NN)
// TB=1: C[m,n] = sum_k A[m,k] * B[n,k]   (NT)
// Optional row bias (bias_m) and col bias (bias_n). blockIdx.z batches.
//
// SMEM layout (element strides, in 4B words):
//   As: 128 rows x stride 44  (44 % 32 = 12 -> frag LDS bank = 12*row+k, all
//       32 lanes distinct; 44 % 4 == 0 -> uint4-aligned staging stores)
//   Bs (TB=1, [n][k]): 128 x stride 44 (same argument)
//   Bs (TB=0, [k][n]): 32 x stride 136 (136 % 32 = 8 -> bank = 8*k+n distinct)
// ---------------------------------------------------------------------------
template <int TB>
__global__ __launch_bounds__(256, 1)
void gemm_mma(const float* __restrict__ A, long lda, long sAz,
              const float* __restrict__ Bm, long ldb, long sBz,
              float* __restrict__ Cm, long ldc, long sCz,
              int Kd,
              const float* __restrict__ bias_m,
              const float* __restrict__ bias_n)
{
    constexpr int ASTRIDE = 44;
    constexpr int BSTRIDE = TB ? 44 : 136;
    constexpr int BSIZE   = TB ? 128 * 44 : 32 * 136;

    __shared__ unsigned As[128 * ASTRIDE];
    __shared__ unsigned Bs[BSIZE];

    A  += (long)blockIdx.z * sAz;
    Bm += (long)blockIdx.z * sBz;
    Cm += (long)blockIdx.z * sCz;
    const int m0 = blockIdx.y * 128;
    const int n0 = blockIdx.x * 128;
    const int tid  = threadIdx.x;
    const int lane = tid & 31;
    const int wid  = tid >> 5;
    const int g  = lane >> 2;     // group id (0..7)
    const int tg = lane & 3;      // thread in group (0..3)
    const int m_w = (wid & 1) * 64;
    const int n_w = (wid >> 1) * 32;

    float acc[4][4][4];
#pragma unroll
    for (int i = 0; i < 4; i++)
#pragma unroll
        for (int j = 0; j < 4; j++)
#pragma unroll
            for (int q = 0; q < 4; q++) acc[i][j][q] = 0.f;

    float4 apf[4], bpf[4];

    auto load_tile = [&](int kt) {
#pragma unroll
        for (int i = 0; i < 4; i++) {
            int lin = i * 256 + tid;
            int r  = lin >> 3;            // 0..127
            int c4 = (lin & 7) * 4;       // 0..28
            apf[i] = *(const float4*)(A + (long)(m0 + r) * lda + kt + c4);
            if (TB) {
                bpf[i] = *(const float4*)(Bm + (long)(n0 + r) * ldb + kt + c4);
            } else {
                int kr = lin >> 5;        // 0..31
                int nc = (lin & 31) * 4;  // 0..124
                bpf[i] = *(const float4*)(Bm + (long)(kt + kr) * ldb + n0 + nc);
            }
        }
    };

    auto stage_tile = [&]() {
#pragma unroll
        for (int i = 0; i < 4; i++) {
            int lin = i * 256 + tid;
            int r  = lin >> 3;
            int c4 = (lin & 7) * 4;
            uint4 av = make_uint4(f2tf32(apf[i].x), f2tf32(apf[i].y),
                                  f2tf32(apf[i].z), f2tf32(apf[i].w));
            *(uint4*)&As[r * ASTRIDE + c4] = av;
            uint4 bvv = make_uint4(f2tf32(bpf[i].x), f2tf32(bpf[i].y),
                                   f2tf32(bpf[i].z), f2tf32(bpf[i].w));
            if (TB) {
                *(uint4*)&Bs[r * BSTRIDE + c4] = bvv;
            } else {
                int kr = lin >> 5;
                int nc = (lin & 31) * 4;
                *(uint4*)&Bs[kr * BSTRIDE + nc] = bvv;
            }
        }
    };

    load_tile(0);

    for (int kt = 0; kt < Kd; kt += 32) {
        __syncthreads();
        stage_tile();
        __syncthreads();
        if (kt + 32 < Kd) load_tile(kt + 32);

#pragma unroll
        for (int kk = 0; kk < 4; kk++) {
            const int kb = kk * 8;
            unsigned af[4][4], bf[4][2];
#pragma unroll
            for (int mt = 0; mt < 4; mt++) {
                int r = m_w + mt * 16 + g;
                af[mt][0] = As[r * ASTRIDE + kb + tg];
                af[mt][1] = As[(r + 8) * ASTRIDE + kb + tg];
                af[mt][2] = As[r * ASTRIDE + kb + tg + 4];
                af[mt][3] = As[(r + 8) * ASTRIDE + kb + tg + 4];
            }
#pragma unroll
            for (int nt = 0; nt < 4; nt++) {
                int n = n_w + nt * 8 + g;
                if (TB) {
                    bf[nt][0] = Bs[n * BSTRIDE + kb + tg];
                    bf[nt][1] = Bs[n * BSTRIDE + kb + tg + 4];
                } else {
                    bf[nt][0] = Bs[(kb + tg) * BSTRIDE + n];
                    bf[nt][1] = Bs[(kb + tg + 4) * BSTRIDE + n];
                }
            }
#pragma unroll
            for (int mt = 0; mt < 4; mt++)
#pragma unroll
                for (int nt = 0; nt < 4; nt++)
                    mma_tf32(acc[mt][nt], af[mt], bf[nt]);
        }
    }

    // Epilogue: c0:(g, 2tg) c1:(g, 2tg+1) c2:(g+8, 2tg) c3:(g+8, 2tg+1)
#pragma unroll
    for (int mt = 0; mt < 4; mt++) {
        int r0 = m0 + m_w + mt * 16 + g;
        float bm0 = bias_m ? bias_m[r0]     : 0.f;
        float bm1 = bias_m ? bias_m[r0 + 8] : 0.f;
#pragma unroll
        for (int nt = 0; nt < 4; nt++) {
            int cc = n0 + n_w + nt * 8 + 2 * tg;
            float bn0 = bias_n ? bias_n[cc]     : 0.f;
            float bn1 = bias_n ? bias_n[cc + 1] : 0.f;
            const float* c = acc[mt][nt];
            *(float2*)(Cm + (long)r0 * ldc + cc) =
                make_float2(c[0] + bm0 + bn0, c[1] + bm0 + bn1);
            *(float2*)(Cm + (long)(r0 + 8) * ldc + cc) =
                make_float2(c[2] + bm1 + bn0, c[3] + bm1 + bn1);
        }
    }
}

// Normalize Ek columns over c: one thread per (k, n); layout [k][c][n].
__global__ void norm_cols_kernel(float* __restrict__ E)
{
    int idx = blockIdx.x * blockDim.x + threadIdx.x;   // 0..2559
    int kk = idx >> 9, n = idx & 511;
    float* base = E + (long)kk * (1024 * 512) + n;
    float s = 0.f;
#pragma unroll 4
    for (int c = 0; c < 1024; c++) { float v = base[(long)c * 512]; s = fmaf(v, v, s); }
    float inv = 1.f / fmaxf(sqrtf(s), 1e-8f);
#pragma unroll 4
    for (int c = 0; c < 1024; c++) base[(long)c * 512] *= inv;
}

// Normalize k rows over c (1024), in place. grid = B, 256 threads.
__global__ void norm_rows_kernel(float* __restrict__ Kb)
{
    int b = blockIdx.x, tid = threadIdx.x;
    float* row = Kb + (long)b * 1024;
    float4 v = *(float4*)&row[tid * 4];
    __shared__ float sred[256];
    sred[tid] = v.x * v.x + v.y * v.y + v.z * v.z + v.w * v.w;
    __syncthreads();
    for (int st = 128; st > 0; st >>= 1) {
        if (tid < st) sred[tid] += sred[tid + st];
        __syncthreads();
    }
    float inv = 1.f / fmaxf(sqrtf(sred[0]), 1e-8f);
    v.x *= inv; v.y *= inv; v.z *= inv; v.w *= inv;
    *(float4*)&row[tid * 4] = v;
}

// Softmax over 512; grid = B*K, 128 threads, in place.
__global__ void softmax_kernel(float* __restrict__ S)
{
    float* base = S + (long)blockIdx.x * 512;
    int tid = threadIdx.x;
    float4 v = *(float4*)&base[tid * 4];
    __shared__ float sred[128];
    sred[tid] = fmaxf(fmaxf(v.x, v.y), fmaxf(v.z, v.w));
    __syncthreads();
    for (int st = 64; st > 0; st >>= 1) {
        if (tid < st) sred[tid] = fmaxf(sred[tid], sred[tid + st]);
        __syncthreads();
    }
    float m = sred[0];
    __syncthreads();
    v.x = expf(v.x - m); v.y = expf(v.y - m); v.z = expf(v.z - m); v.w = expf(v.w - m);
    sred[tid] = v.x + v.y + v.z + v.w;
    __syncthreads();
    for (int st = 64; st > 0; st >>= 1) {
        if (tid < st) sred[tid] += sred[tid + st];
        __syncthreads();
    }
    float inv = 1.f / sred[0];
    v.x *= inv; v.y *= inv; v.z *= inv; v.w *= inv;
    *(float4*)&base[tid * 4] = v;
}

// Gate + concat + output GEMV per batch row. grid = B, 256 threads.
__global__ void final_kernel(const float* __restrict__ vbuf,
                             const float* __restrict__ fe,
                             const float* __restrict__ Ww,
                             const float* __restrict__ bw,
                             const float* __restrict__ Wout,
                             const float* __restrict__ bout,
                             float* __restrict__ out)
{
    const int b = blockIdx.x, tid = threadIdx.x;
    const long bc = (long)b * 1024;
    const long sz = (long)4096 * 1024;
    __shared__ float sred[256];
    __shared__ float s_fw[5];

    float acc[5] = {0.f, 0.f, 0.f, 0.f, 0.f};
    for (int c = tid; c < 1024; c += 256) {
        float wv = Ww[c];
#pragma unroll
        for (int kk = 0; kk < 5; kk++)
            acc[kk] = fmaf(wv, fe[sz * kk + bc + c], acc[kk]);
    }
#pragma unroll
    for (int kk = 0; kk < 5; kk++) {
        __syncthreads();
        sred[tid] = acc[kk];
        __syncthreads();
        for (int st = 128; st > 0; st >>= 1) {
            if (tid < st) sred[tid] += sred[tid + st];
            __syncthreads();
        }
        if (tid == 0) s_fw[kk] = 1.f / (1.f + expf(-(sred[0] + bw[0])));
    }
    __syncthreads();
    float fwl[5];
#pragma unroll
    for (int kk = 0; kk < 5; kk++) fwl[kk] = s_fw[kk];

    float oacc[5] = {0.f, 0.f, 0.f, 0.f, 0.f};
    for (int j = tid; j < 2048; j += 256) {
        float h;
        if (j < 1024) {
            h = vbuf[bc + j];
        } else {
            int c = j - 1024;
            float s = 0.f;
#pragma unroll
            for (int kk = 0; kk < 5; kk++)
                s = fmaf(fe[sz * kk + bc + c], fwl[kk], s);
            h = s;
        }
        h = fmaxf(h, 0.f);
#pragma unroll
        for (int kk = 0; kk < 5; kk++)
            oacc[kk] = fmaf(h, Wout[kk * 2048 + j], oacc[kk]);
    }
#pragma unroll
    for (int kk = 0; kk < 5; kk++) {
        __syncthreads();
        sred[tid] = oacc[kk];
        __syncthreads();
        for (int st = 128; st > 0; st >>= 1) {
            if (tid < st) sred[tid] += sred[tid + st];
            __syncthreads();
        }
        if (tid == 0) out[b * 5 + kk] = sred[0] + bout[kk];
    }
}

extern "C" void kernel_launch(void* const* d_in, const int* in_sizes, int n_in,
                              void* d_out, int out_size)
{
    const float* x    = (const float*)d_in[0];   // (4096, 8, 2048)
    const float* stat = (const float*)d_in[1];   // (5, 2048, 512)
    const float* Wk   = (const float*)d_in[2];   // (1024, 2048)
    const float* bk   = (const float*)d_in[3];
    const float* Wv   = (const float*)d_in[4];
    const float* bv   = (const float*)d_in[5];
    const float* WEk  = (const float*)d_in[6];
    const float* bEk  = (const float*)d_in[7];
    const float* WEv  = (const float*)d_in[8];
    const float* bEv  = (const float*)d_in[9];
    const float* Ww   = (const float*)d_in[10];  // (1, 1024)
    const float* bw   = (const float*)d_in[11];  // (1,)
    const float* Wout = (const float*)d_in[12];  // (5, 2048)
    const float* bout = (const float*)d_in[13];  // (5,)
    float* out = (float*)d_out;                  // (4096, 5, 1)

    float *k_, *v_, *Ek_, *Ev_, *sim_, *fe_;
    cudaGetSymbolAddress((void**)&k_,   g_k);
    cudaGetSymbolAddress((void**)&v_,   g_v);
    cudaGetSymbolAddress((void**)&Ek_,  g_Ek);
    cudaGetSymbolAddress((void**)&Ev_,  g_Ev);
    cudaGetSymbolAddress((void**)&sim_, g_sim);
    cudaGetSymbolAddress((void**)&fe_,  g_fe);

    // k = x_last @ Wk^T + bk ; v = x_last @ Wv^T + bv  (NT, M=4096 N=1024 K=2048)
    gemm_mma<1><<<dim3(8, 32, 1), 256>>>(x + 7 * 2048, 8 * 2048, 0,
                                         Wk, 2048, 0, k_, 1024, 0, 2048, nullptr, bk);
    gemm_mma<1><<<dim3(8, 32, 1), 256>>>(x + 7 * 2048, 8 * 2048, 0,
                                         Wv, 2048, 0, v_, 1024, 0, 2048, nullptr, bv);

    // Ek[z] = WEk @ static[z] + bEk (row bias); Ev likewise (NN, 1024x512x2048, z=5)
    gemm_mma<0><<<dim3(4, 8, 5), 256>>>(WEk, 2048, 0,
                                        stat, 512, (long)2048 * 512,
                                        Ek_, 512, (long)1024 * 512, 2048, bEk, nullptr);
    gemm_mma<0><<<dim3(4, 8, 5), 256>>>(WEv, 2048, 0,
                                        stat, 512, (long)2048 * 512,
                                        Ev_, 512, (long)1024 * 512, 2048, bEv, nullptr);

    norm_cols_kernel<<<(5 * 512) / 128, 128>>>(Ek_);   // Ek -> Ekn in place
    norm_rows_kernel<<<4096, 256>>>(k_);               // k  -> kn  in place

    // sim[b][z][n] = kn @ Ekn[z]  (NN, M=4096 N=512 K=1024, z=5), C row stride 2560
    gemm_mma<0><<<dim3(4, 32, 5), 256>>>(k_, 1024, 0,
                                         Ek_, 512, (long)1024 * 512,
                                         sim_, 5 * 512, 512, 1024, nullptr, nullptr);

    softmax_kernel<<<4096 * 5, 128>>>(sim_);           // sim -> w in place

    // fe[z][b][c] = w[:,z,:] @ Ev[z]^T (NT, M=4096 N=1024 K=512, z=5)
    gemm_mma<1><<<dim3(8, 32, 5), 256>>>(sim_, 5 * 512, 512,
                                         Ev_, 512, (long)1024 * 512,
                                         fe_, 1024, (long)4096 * 1024, 512, nullptr, nullptr);

    final_kernel<<<4096, 256>>>(v_, fe_, Ww, bw, Wout, bout, out);
}

// round 4
// speedup vs baseline: 3.0414x; 1.3109x over previous
#include <cuda_runtime.h>
#include <math.h>

// Problem dims (fixed): B=4096, T=8, CH_IN=2048, C=1024, N=512, K=5, EPS=1e-8

__device__ float g_k  [4096u * 1024u];          // k fp32, then kn (tf32 bits) in place
__device__ float g_v  [4096u * 1024u];          // v fp32
__device__ float g_Ek [5u * 1024u * 512u];      // Ek (tf32 bits, bias added)
__device__ float g_Ev [5u * 1024u * 512u];      // Ev (tf32 bits, bias added)
__device__ float g_sim[4096u * 5u * 512u];      // sim fp32, then w (tf32 bits) in place
__device__ float g_fe [5u * 4096u * 1024u];     // feature_E fp32, [k][b][c]
__device__ float g_invE[5u * 512u];             // 1/max(||Ek col||, eps)
__device__ float g_xl [4096u * 2048u];          // x_last, tf32 bits
__device__ float g_wtf[4u * 1024u * 2048u];     // Wk|Wv|WEk|WEv, tf32 bits
__device__ float g_stf[5u * 2048u * 512u];      // static, tf32 bits

#define DINLINE __device__ __forceinline__

DINLINE unsigned f2tf32(float f) {
    unsigned u;
    asm("cvt.rna.tf32.f32 %0, %1;" : "=r"(u) : "f"(f));
    return u;
}

DINLINE void mma_tf32(float* c, const unsigned* a, const unsigned* b) {
    asm volatile(
        "mma.sync.aligned.m16n8k8.row.col.f32.tf32.tf32.f32 "
        "{%0,%1,%2,%3}, {%4,%5,%6,%7}, {%8,%9}, {%0,%1,%2,%3};"
        : "+f"(c[0]), "+f"(c[1]), "+f"(c[2]), "+f"(c[3])
        : "r"(a[0]), "r"(a[1]), "r"(a[2]), "r"(a[3]),
          "r"(b[0]), "r"(b[1]));
}

DINLINE void cp16(void* dst_smem, const void* src) {
    unsigned d = (unsigned)__cvta_generic_to_shared(dst_smem);
    asm volatile("cp.async.cg.shared.global [%0], [%1], 16;" :: "r"(d), "l"(src));
}
DINLINE void cp_commit() { asm volatile("cp.async.commit_group;"); }
DINLINE void cp_wait1()  { asm volatile("cp.async.wait_group 1;"); }
DINLINE void cp_wait0()  { asm volatile("cp.async.wait_group 0;"); }

// ---------------------------------------------------------------------------
// TF32 tensor-core GEMM, cp.async 3-stage pipeline.
// 128x128x32 block tile, 256 threads (2x4 warps), warp = 64x32 (m16n8k8 frags).
// Operands must already be tf32-rounded bit patterns.
// TB=0: C=A*B (NN), TB=1: C=A*B^T (NT). EPI=1: store tf32 bits instead of fp32.
// SMEM strides (words): A=36 (36%32=4 -> frag bank 4g+tg unique; %4==0 for cp16)
//                       B_NT=36 (same), B_NN=136 (136%32=8 -> 8tg+g unique).
// ---------------------------------------------------------------------------
template <int TB, int EPI>
__global__ __launch_bounds__(256, 2)
void gemm_cp(const float* __restrict__ A, long lda, long sAz,
             const float* __restrict__ Bm, long ldb, long sBz,
             float* __restrict__ Cm, long ldc, long sCz,
             int Kd,
             const float* __restrict__ bias_m,
             const float* __restrict__ bias_n)
{
    constexpr int AST = 36;
    constexpr int BST = TB ? 36 : 136;
    constexpr int AWORDS = 128 * AST;                 // 4608
    constexpr int BWORDS = TB ? 128 * 36 : 32 * 136;  // 4608 / 4352
    constexpr int STAGE  = AWORDS + BWORDS;

    extern __shared__ unsigned sh[];

    A  += (long)blockIdx.z * sAz;
    Bm += (long)blockIdx.z * sBz;
    Cm += (long)blockIdx.z * sCz;
    const int m0 = blockIdx.y * 128;
    const int n0 = blockIdx.x * 128;
    const int tid  = threadIdx.x;
    const int lane = tid & 31;
    const int wid  = tid >> 5;
    const int g  = lane >> 2;
    const int tg = lane & 3;
    const int m_w = (wid & 1) * 64;
    const int n_w = (wid >> 1) * 32;

    float acc[4][4][4];
#pragma unroll
    for (int i = 0; i < 4; i++)
#pragma unroll
        for (int j = 0; j < 4; j++)
#pragma unroll
            for (int q = 0; q < 4; q++) acc[i][j][q] = 0.f;

    auto issue = [&](int kt, int s) {
        unsigned* As = sh + s * STAGE;
        unsigned* Bs = As + AWORDS;
#pragma unroll
        for (int i = 0; i < 4; i++) {
            int lin = i * 256 + tid;
            int r  = lin >> 3;
            int c4 = (lin & 7) * 4;
            cp16(&As[r * AST + c4], A + (long)(m0 + r) * lda + kt + c4);
            if (TB) {
                cp16(&Bs[r * BST + c4], Bm + (long)(n0 + r) * ldb + kt + c4);
            } else {
                int kr = lin >> 5;
                int nc = (lin & 31) * 4;
                cp16(&Bs[kr * BST + nc], Bm + (long)(kt + kr) * ldb + n0 + nc);
            }
        }
        cp_commit();
    };

    const int KT = Kd >> 5;            // >= 16 for all our shapes
    issue(0, 0);
    issue(32, 1);

    for (int t = 0; t < KT; t++) {
        cp_wait1();
        __syncthreads();
        int tn = t + 2;
        issue(tn < KT ? tn * 32 : 0, (t + 2) % 3);   // dummy reload at tail

        const unsigned* As = sh + (t % 3) * STAGE;
        const unsigned* Bs = As + AWORDS;
#pragma unroll
        for (int kk = 0; kk < 4; kk++) {
            const int kb = kk * 8;
            unsigned af[4][4], bf[4][2];
#pragma unroll
            for (int mt = 0; mt < 4; mt++) {
                int r = m_w + mt * 16 + g;
                af[mt][0] = As[r * AST + kb + tg];
                af[mt][1] = As[(r + 8) * AST + kb + tg];
                af[mt][2] = As[r * AST + kb + tg + 4];
                af[mt][3] = As[(r + 8) * AST + kb + tg + 4];
            }
#pragma unroll
            for (int nt = 0; nt < 4; nt++) {
                int n = n_w + nt * 8 + g;
                if (TB) {
                    bf[nt][0] = Bs[n * BST + kb + tg];
                    bf[nt][1] = Bs[n * BST + kb + tg + 4];
                } else {
                    bf[nt][0] = Bs[(kb + tg) * BST + n];
                    bf[nt][1] = Bs[(kb + tg + 4) * BST + n];
                }
            }
#pragma unroll
            for (int mt = 0; mt < 4; mt++)
#pragma unroll
                for (int nt = 0; nt < 4; nt++)
                    mma_tf32(acc[mt][nt], af[mt], bf[nt]);
        }
    }
    cp_wait0();   // drain dummy groups before CTA exit

    // Epilogue: c0:(g,2tg) c1:(g,2tg+1) c2:(g+8,2tg) c3:(g+8,2tg+1)
#pragma unroll
    for (int mt = 0; mt < 4; mt++) {
        int r0 = m0 + m_w + mt * 16 + g;
        float bm0 = bias_m ? bias_m[r0]     : 0.f;
        float bm1 = bias_m ? bias_m[r0 + 8] : 0.f;
#pragma unroll
        for (int nt = 0; nt < 4; nt++) {
            int cc = n0 + n_w + nt * 8 + 2 * tg;
            float bn0 = bias_n ? bias_n[cc]     : 0.f;
            float bn1 = bias_n ? bias_n[cc + 1] : 0.f;
            const float* c = acc[mt][nt];
            float v00 = c[0] + bm0 + bn0, v01 = c[1] + bm0 + bn1;
            float v10 = c[2] + bm1 + bn0, v11 = c[3] + bm1 + bn1;
            if (EPI) {
                v00 = __uint_as_float(f2tf32(v00));
                v01 = __uint_as_float(f2tf32(v01));
                v10 = __uint_as_float(f2tf32(v10));
                v11 = __uint_as_float(f2tf32(v11));
            }
            *(float2*)(Cm + (long)r0 * ldc + cc)       = make_float2(v00, v01);
            *(float2*)(Cm + (long)(r0 + 8) * ldc + cc) = make_float2(v10, v11);
        }
    }
}

// --- tf32 pre-conversion -----------------------------------------------------
__global__ void cvt4_kernel(const float4* __restrict__ in, uint4* __restrict__ out, int n4)
{
    int i = blockIdx.x * blockDim.x + threadIdx.x;
    if (i < n4) {
        float4 v = in[i];
        out[i] = make_uint4(f2tf32(v.x), f2tf32(v.y), f2tf32(v.z), f2tf32(v.w));
    }
}

// gather x[:, 7, :] -> contiguous tf32
__global__ void gather_x_kernel(const float* __restrict__ x, uint4* __restrict__ out)
{
    int i = blockIdx.x * blockDim.x + threadIdx.x;    // float4 index, 4096*512 total
    int b  = i >> 9;
    int c4 = (i & 511) * 4;
    float4 v = *(const float4*)(x + (long)b * 16384 + 14336 + c4);
    out[(long)b * 512 + (i & 511)] =
        make_uint4(f2tf32(v.x), f2tf32(v.y), f2tf32(v.z), f2tf32(v.w));
}

// inv col-norms of Ek: grid (4 ntiles, 5 z), 512 threads
__global__ void ssqE_kernel(const float* __restrict__ E, float* __restrict__ invE)
{
    int z = blockIdx.y;
    int nx = threadIdx.x & 127;
    int cg = threadIdx.x >> 7;
    int n = blockIdx.x * 128 + nx;
    const float* base = E + (long)z * (1024 * 512) + n;
    float s = 0.f;
#pragma unroll 8
    for (int c = cg; c < 1024; c += 4) {
        float v = base[(long)c * 512];
        s = fmaf(v, v, s);
    }
    __shared__ float red[512];
    red[threadIdx.x] = s;
    __syncthreads();
    if (cg == 0) {
        s = red[nx] + red[nx + 128] + red[nx + 256] + red[nx + 384];
        invE[z * 512 + n] = 1.f / fmaxf(sqrtf(s), 1e-8f);
    }
}

// normalize k rows (1024) in place, write tf32 bits. grid=B, 256 thr.
__global__ void norm_rows_kernel(float* __restrict__ Kb)
{
    int b = blockIdx.x, tid = threadIdx.x;
    float* row = Kb + (long)b * 1024;
    float4 v = *(float4*)&row[tid * 4];
    __shared__ float sred[256];
    sred[tid] = v.x * v.x + v.y * v.y + v.z * v.z + v.w * v.w;
    __syncthreads();
    for (int st = 128; st > 0; st >>= 1) {
        if (tid < st) sred[tid] += sred[tid + st];
        __syncthreads();
    }
    float inv = 1.f / fmaxf(sqrtf(sred[0]), 1e-8f);
    *(uint4*)&row[tid * 4] = make_uint4(f2tf32(v.x * inv), f2tf32(v.y * inv),
                                        f2tf32(v.z * inv), f2tf32(v.w * inv));
}

// scale by invE[z,n], softmax over 512, write tf32 bits in place.
// grid = B*K (row = b*5+z), 128 threads.
__global__ void softmax_kernel(float* __restrict__ S, const float* __restrict__ invE)
{
    int row = blockIdx.x;
    int z = row % 5;
    float* base = S + (long)row * 512;
    int tid = threadIdx.x;
    float4 v = *(float4*)&base[tid * 4];
    float4 e = *(const float4*)&invE[z * 512 + tid * 4];
    v.x *= e.x; v.y *= e.y; v.z *= e.z; v.w *= e.w;
    __shared__ float sred[128];
    sred[tid] = fmaxf(fmaxf(v.x, v.y), fmaxf(v.z, v.w));
    __syncthreads();
    for (int st = 64; st > 0; st >>= 1) {
        if (tid < st) sred[tid] = fmaxf(sred[tid], sred[tid + st]);
        __syncthreads();
    }
    float m = sred[0];
    __syncthreads();
    v.x = expf(v.x - m); v.y = expf(v.y - m); v.z = expf(v.z - m); v.w = expf(v.w - m);
    sred[tid] = v.x + v.y + v.z + v.w;
    __syncthreads();
    for (int st = 64; st > 0; st >>= 1) {
        if (tid < st) sred[tid] += sred[tid + st];
        __syncthreads();
    }
    float inv = 1.f / sred[0];
    *(uint4*)&base[tid * 4] = make_uint4(f2tf32(v.x * inv), f2tf32(v.y * inv),
                                         f2tf32(v.z * inv), f2tf32(v.w * inv));
}

// Gate + concat + output GEMV per batch row. grid = B, 256 threads.
__global__ void final_kernel(const float* __restrict__ vbuf,
                             const float* __restrict__ fe,
                             const float* __restrict__ Ww,
                             const float* __restrict__ bw,
                             const float* __restrict__ Wout,
                             const float* __restrict__ bout,
                             float* __restrict__ out)
{
    const int b = blockIdx.x, tid = threadIdx.x;
    const long bc = (long)b * 1024;
    const long sz = (long)4096 * 1024;
    __shared__ float sred[256];
    __shared__ float s_fw[5];

    float acc[5] = {0.f, 0.f, 0.f, 0.f, 0.f};
    for (int c = tid; c < 1024; c += 256) {
        float wv = Ww[c];
#pragma unroll
        for (int kk = 0; kk < 5; kk++)
            acc[kk] = fmaf(wv, fe[sz * kk + bc + c], acc[kk]);
    }
#pragma unroll
    for (int kk = 0; kk < 5; kk++) {
        __syncthreads();
        sred[tid] = acc[kk];
        __syncthreads();
        for (int st = 128; st > 0; st >>= 1) {
            if (tid < st) sred[tid] += sred[tid + st];
            __syncthreads();
        }
        if (tid == 0) s_fw[kk] = 1.f / (1.f + expf(-(sred[0] + bw[0])));
    }
    __syncthreads();
    float fwl[5];
#pragma unroll
    for (int kk = 0; kk < 5; kk++) fwl[kk] = s_fw[kk];

    float oacc[5] = {0.f, 0.f, 0.f, 0.f, 0.f};
    for (int j = tid; j < 2048; j += 256) {
        float h;
        if (j < 1024) {
            h = vbuf[bc + j];
        } else {
            int c = j - 1024;
            float s = 0.f;
#pragma unroll
            for (int kk = 0; kk < 5; kk++)
                s = fmaf(fe[sz * kk + bc + c], fwl[kk], s);
            h = s;
        }
        h = fmaxf(h, 0.f);
#pragma unroll
        for (int kk = 0; kk < 5; kk++)
            oacc[kk] = fmaf(h, Wout[kk * 2048 + j], oacc[kk]);
    }
#pragma unroll
    for (int kk = 0; kk < 5; kk++) {
        __syncthreads();
        sred[tid] = oacc[kk];
        __syncthreads();
        for (int st = 128; st > 0; st >>= 1) {
            if (tid < st) sred[tid] += sred[tid + st];
            __syncthreads();
        }
        if (tid == 0) out[b * 5 + kk] = sred[0] + bout[kk];
    }
}

extern "C" void kernel_launch(void* const* d_in, const int* in_sizes, int n_in,
                              void* d_out, int out_size)
{
    const float* x    = (const float*)d_in[0];   // (4096, 8, 2048)
    const float* stat = (const float*)d_in[1];   // (5, 2048, 512)
    const float* Wk   = (const float*)d_in[2];   // (1024, 2048)
    const float* bk   = (const float*)d_in[3];
    const float* Wv   = (const float*)d_in[4];
    const float* bv   = (const float*)d_in[5];
    const float* WEk  = (const float*)d_in[6];
    const float* bEk  = (const float*)d_in[7];
    const float* WEv  = (const float*)d_in[8];
    const float* bEv  = (const float*)d_in[9];
    const float* Ww   = (const float*)d_in[10];
    const float* bw   = (const float*)d_in[11];
    const float* Wout = (const float*)d_in[12];  // (5, 2048)
    const float* bout = (const float*)d_in[13];
    float* out = (float*)d_out;                  // (4096, 5, 1)

    float *k_, *v_, *Ek_, *Ev_, *sim_, *fe_, *invE_, *xl_, *wtf_, *stf_;
    cudaGetSymbolAddress((void**)&k_,   g_k);
    cudaGetSymbolAddress((void**)&v_,   g_v);
    cudaGetSymbolAddress((void**)&Ek_,  g_Ek);
    cudaGetSymbolAddress((void**)&Ev_,  g_Ev);
    cudaGetSymbolAddress((void**)&sim_, g_sim);
    cudaGetSymbolAddress((void**)&fe_,  g_fe);
    cudaGetSymbolAddress((void**)&invE_, g_invE);
    cudaGetSymbolAddress((void**)&xl_,  g_xl);
    cudaGetSymbolAddress((void**)&wtf_, g_wtf);
    cudaGetSymbolAddress((void**)&stf_, g_stf);

    constexpr int SM_NT = (4608 + 4608) * 3 * 4;  // 110592 B
    constexpr int SM_NN = (4608 + 4352) * 3 * 4;  // 107520 B
    cudaFuncSetAttribute(gemm_cp<1, 0>, cudaFuncAttributeMaxDynamicSharedMemorySize, SM_NT);
    cudaFuncSetAttribute(gemm_cp<0, 0>, cudaFuncAttributeMaxDynamicSharedMemorySize, SM_NN);
    cudaFuncSetAttribute(gemm_cp<0, 1>, cudaFuncAttributeMaxDynamicSharedMemorySize, SM_NN);

    // ---- pre-convert operands to tf32 ----
    gather_x_kernel<<<(4096 * 512) / 256, 256>>>(x, (uint4*)xl_);
    cvt4_kernel<<<(1024 * 2048 / 4 + 255) / 256, 256>>>((const float4*)Wk,
                                                        (uint4*)(wtf_ + 0L * 1024 * 2048), 1024 * 2048 / 4);
    cvt4_kernel<<<(1024 * 2048 / 4 + 255) / 256, 256>>>((const float4*)Wv,
                                                        (uint4*)(wtf_ + 1L * 1024 * 2048), 1024 * 2048 / 4);
    cvt4_kernel<<<(1024 * 2048 / 4 + 255) / 256, 256>>>((const float4*)WEk,
                                                        (uint4*)(wtf_ + 2L * 1024 * 2048), 1024 * 2048 / 4);
    cvt4_kernel<<<(1024 * 2048 / 4 + 255) / 256, 256>>>((const float4*)WEv,
                                                        (uint4*)(wtf_ + 3L * 1024 * 2048), 1024 * 2048 / 4);
    cvt4_kernel<<<(5 * 2048 * 512 / 4 + 255) / 256, 256>>>((const float4*)stat,
                                                           (uint4*)stf_, 5 * 2048 * 512 / 4);

    // ---- k, v (NT, M=4096 N=1024 K=2048), fp32 out ----
    gemm_cp<1, 0><<<dim3(8, 32, 1), 256, SM_NT>>>(xl_, 2048, 0,
                                                  wtf_ + 0L * 1024 * 2048, 2048, 0,
                                                  k_, 1024, 0, 2048, nullptr, bk);
    gemm_cp<1, 0><<<dim3(8, 32, 1), 256, SM_NT>>>(xl_, 2048, 0,
                                                  wtf_ + 1L * 1024 * 2048, 2048, 0,
                                                  v_, 1024, 0, 2048, nullptr, bv);

    // ---- Ek, Ev (NN, M=1024 N=512 K=2048, z=5), tf32 out, row bias ----
    gemm_cp<0, 1><<<dim3(4, 8, 5), 256, SM_NN>>>(wtf_ + 2L * 1024 * 2048, 2048, 0,
                                                 stf_, 512, (long)2048 * 512,
                                                 Ek_, 512, (long)1024 * 512, 2048, bEk, nullptr);
    gemm_cp<0, 1><<<dim3(4, 8, 5), 256, SM_NN>>>(wtf_ + 3L * 1024 * 2048, 2048, 0,
                                                 stf_, 512, (long)2048 * 512,
                                                 Ev_, 512, (long)1024 * 512, 2048, bEv, nullptr);

    ssqE_kernel<<<dim3(4, 5), 512>>>(Ek_, invE_);   // inv col norms (on tf32 values)
    norm_rows_kernel<<<4096, 256>>>(k_);            // k -> kn (tf32 bits) in place

    // ---- sim = kn @ Ek (NN, M=4096 N=512 K=1024, z=5), fp32 out, ldc=2560 ----
    gemm_cp<0, 0><<<dim3(4, 32, 5), 256, SM_NN>>>(k_, 1024, 0,
                                                  Ek_, 512, (long)1024 * 512,
                                                  sim_, 5 * 512, 512, 1024, nullptr, nullptr);

    softmax_kernel<<<4096 * 5, 128>>>(sim_, invE_); // scale, softmax, tf32 out in place

    // ---- fe = w @ Ev^T (NT, M=4096 N=1024 K=512, z=5), fp32 out ----
    gemm_cp<1, 0><<<dim3(8, 32, 5), 256, SM_NT>>>(sim_, 5 * 512, 512,
                                                  Ev_, 512, (long)1024 * 512,
                                                  fe_, 1024, (long)4096 * 1024, 512, nullptr, nullptr);

    final_kernel<<<4096, 256>>>(v_, fe_, Ww, bw, Wout, bout, out);
}

// round 5
// speedup vs baseline: 3.3939x; 1.1159x over previous
#include <cuda_runtime.h>
#include <math.h>

// Problem dims (fixed): B=4096, T=8, CH_IN=2048, C=1024, N=512, K=5, EPS=1e-8

__device__ float g_kv [4096u * 2048u];          // [k | v] fp32; k cols 0-1023 -> kn tf32 in place
__device__ float g_EkT[5u * 512u * 1024u];      // EkT [z][n][c], tf32 bits (bias added)
__device__ float g_Ev [5u * 1024u * 512u];      // Ev  [z][c][n], tf32 bits (bias added)
__device__ float g_sim[4096u * 5u * 512u];      // sim fp32, then w (tf32 bits) in place
__device__ float g_fe [5u * 4096u * 1024u];     // feature_E fp32, [z][b][c]
__device__ float g_invE[5u * 512u];             // 1/max(||Ek col||, eps)
__device__ float g_xl [4096u * 2048u];          // x_last, tf32 bits
__device__ float g_wtf[4u * 1024u * 2048u];     // Wk|Wv|WEk|WEv, tf32 bits (Wk,Wv contiguous)
__device__ float g_stT[5u * 512u * 2048u];      // static transposed [z][n][i], tf32 bits
__device__ float g_bkv[2048u];                  // bk | bv

#define DINLINE __device__ __forceinline__

DINLINE unsigned f2tf32(float f) {
    unsigned u;
    asm("cvt.rna.tf32.f32 %0, %1;" : "=r"(u) : "f"(f));
    return u;
}

DINLINE void mma_tf32(float* c, const unsigned* a, const unsigned* b) {
    asm volatile(
        "mma.sync.aligned.m16n8k8.row.col.f32.tf32.tf32.f32 "
        "{%0,%1,%2,%3}, {%4,%5,%6,%7}, {%8,%9}, {%0,%1,%2,%3};"
        : "+f"(c[0]), "+f"(c[1]), "+f"(c[2]), "+f"(c[3])
        : "r"(a[0]), "r"(a[1]), "r"(a[2]), "r"(a[3]),
          "r"(b[0]), "r"(b[1]));
}

DINLINE void ldsm4(unsigned& r0, unsigned& r1, unsigned& r2, unsigned& r3, unsigned saddr) {
    asm volatile("ldmatrix.sync.aligned.m8n8.x4.shared.b16 {%0,%1,%2,%3}, [%4];"
                 : "=r"(r0), "=r"(r1), "=r"(r2), "=r"(r3) : "r"(saddr));
}

DINLINE void cp16(void* dst_smem, const void* src) {
    unsigned d = (unsigned)__cvta_generic_to_shared(dst_smem);
    asm volatile("cp.async.cg.shared.global [%0], [%1], 16;" :: "r"(d), "l"(src));
}
DINLINE void cp_commit() { asm volatile("cp.async.commit_group;"); }
DINLINE void cp_wait1()  { asm volatile("cp.async.wait_group 1;"); }
DINLINE void cp_wait0()  { asm volatile("cp.async.wait_group 0;"); }

// ---------------------------------------------------------------------------
// TF32 NT GEMM (C = A * B^T), cp.async 3-stage pipeline + ldmatrix fragments.
// 128x128x32 block tile, 256 threads (2x4 warps), warp = 64x32 m16n8k8.
// Both A and B stored K-major in SMEM, stride 36 words (pad: 36%32=4 ->
// LDSM rows land on distinct bank groups; 36%4==0 -> cp16-aligned).
// Operands are pre-rounded tf32 bit patterns. EPI=1: store tf32 bits.
// ---------------------------------------------------------------------------
template <int EPI>
__global__ __launch_bounds__(256, 2)
void gemm_nt(const float* __restrict__ A, long lda, long sAz,
             const float* __restrict__ Bm, long ldb, long sBz,
             float* __restrict__ Cm, long ldc, long sCz,
             int Kd,
             const float* __restrict__ bias_m,
             const float* __restrict__ bias_n)
{
    constexpr int ST = 36;
    constexpr int HALF = 128 * ST;            // words per operand per stage
    constexpr int STAGE = 2 * HALF;           // 9216 words

    extern __shared__ unsigned sh[];

    A  += (long)blockIdx.z * sAz;
    Bm += (long)blockIdx.z * sBz;
    Cm += (long)blockIdx.z * sCz;
    const int m0 = blockIdx.y * 128;
    const int n0 = blockIdx.x * 128;
    const int tid  = threadIdx.x;
    const int lane = tid & 31;
    const int wid  = tid >> 5;
    const int g  = lane >> 2;
    const int tg = lane & 3;
    const int m_w = (wid & 1) * 64;
    const int n_w = (wid >> 1) * 32;

    // LDSM per-thread address roles
    const int rr = lane & 7, q = lane >> 3;
    const int arow = ((q & 1) << 3) + rr;     // A: +0/8 row, col 0/4
    const int acol = (q >> 1) << 2;
    const int brow = ((q >> 1) << 3) + rr;    // B: +0/8 row, col 0/4
    const int bcol = (q & 1) << 2;

    const unsigned shb = (unsigned)__cvta_generic_to_shared(sh);
    unsigned aoff[4], boff[2];
#pragma unroll
    for (int mt = 0; mt < 4; mt++)
        aoff[mt] = ((m_w + mt * 16 + arow) * ST + acol) * 4;
#pragma unroll
    for (int nt2 = 0; nt2 < 2; nt2++)
        boff[nt2] = (HALF + (n_w + nt2 * 16 + brow) * ST + bcol) * 4;

    float acc[4][4][4];
#pragma unroll
    for (int i = 0; i < 4; i++)
#pragma unroll
        for (int j = 0; j < 4; j++)
#pragma unroll
            for (int p = 0; p < 4; p++) acc[i][j][p] = 0.f;

    const int r  = tid >> 1;            // 0..127
    const int c4 = (tid & 1) * 4;       // cp row-chunk base (x4 below)

    auto issue = [&](int kt, int s) {
        unsigned* As = sh + s * STAGE;
        unsigned* Bs = As + HALF;
#pragma unroll
        for (int i = 0; i < 4; i++) {
            // 256 threads x 4: each (r, c4+8i? ) -> cover 128 rows x 8 chunks
            int lin = i * 256 + tid;
            int rw  = lin >> 3;
            int cw  = (lin & 7) * 4;
            cp16(&As[rw * ST + cw], A + (long)(m0 + rw) * lda + kt + cw);
            cp16(&Bs[rw * ST + cw], Bm + (long)(n0 + rw) * ldb + kt + cw);
        }
        cp_commit();
    };
    (void)r; (void)c4;

    const int KT = Kd >> 5;
    issue(0, 0);
    issue(32, 1);

    for (int t = 0; t < KT; t++) {
        cp_wait1();
        __syncthreads();
        int tn = t + 2;
        issue(tn < KT ? tn * 32 : 0, (t + 2) % 3);

        const unsigned stb = shb + (t % 3) * (STAGE * 4);
#pragma unroll
        for (int kk = 0; kk < 4; kk++) {
            const unsigned kb = kk * 32;  // 8 words
            unsigned af[4][4], bf[4][2];
#pragma unroll
            for (int mt = 0; mt < 4; mt++)
                ldsm4(af[mt][0], af[mt][1], af[mt][2], af[mt][3], stb + aoff[mt] + kb);
#pragma unroll
            for (int nt2 = 0; nt2 < 2; nt2++)
                ldsm4(bf[2 * nt2][0], bf[2 * nt2][1],
                      bf[2 * nt2 + 1][0], bf[2 * nt2 + 1][1], stb + boff[nt2] + kb);
#pragma unroll
            for (int mt = 0; mt < 4; mt++)
#pragma unroll
                for (int nt = 0; nt < 4; nt++)
                    mma_tf32(acc[mt][nt], af[mt], bf[nt]);
        }
    }
    cp_wait0();

    // Epilogue: c0:(g,2tg) c1:(g,2tg+1) c2:(g+8,2tg) c3:(g+8,2tg+1)
#pragma unroll
    for (int mt = 0; mt < 4; mt++) {
        int r0 = m0 + m_w + mt * 16 + g;
        float bm0 = bias_m ? bias_m[r0]     : 0.f;
        float bm1 = bias_m ? bias_m[r0 + 8] : 0.f;
#pragma unroll
        for (int nt = 0; nt < 4; nt++) {
            int cc = n0 + n_w + nt * 8 + 2 * tg;
            float bn0 = bias_n ? bias_n[cc]     : 0.f;
            float bn1 = bias_n ? bias_n[cc + 1] : 0.f;
            const float* c = acc[mt][nt];
            float v00 = c[0] + bm0 + bn0, v01 = c[1] + bm0 + bn1;
            float v10 = c[2] + bm1 + bn0, v11 = c[3] + bm1 + bn1;
            if (EPI) {
                v00 = __uint_as_float(f2tf32(v00));
                v01 = __uint_as_float(f2tf32(v01));
                v10 = __uint_as_float(f2tf32(v10));
                v11 = __uint_as_float(f2tf32(v11));
            }
            *(float2*)(Cm + (long)r0 * ldc + cc)       = make_float2(v00, v01);
            *(float2*)(Cm + (long)(r0 + 8) * ldc + cc) = make_float2(v10, v11);
        }
    }
}

// --- pre-processing ---------------------------------------------------------
__global__ void cvt4_kernel(const float4* __restrict__ in, uint4* __restrict__ out, int n4)
{
    int i = blockIdx.x * blockDim.x + threadIdx.x;
    if (i < n4) {
        float4 v = in[i];
        out[i] = make_uint4(f2tf32(v.x), f2tf32(v.y), f2tf32(v.z), f2tf32(v.w));
    }
}

__global__ void gather_x_kernel(const float* __restrict__ x, uint4* __restrict__ out)
{
    int i = blockIdx.x * blockDim.x + threadIdx.x;    // float4 index over 4096*512
    int b  = i >> 9;
    int c4 = (i & 511) * 4;
    float4 v = *(const float4*)(x + (long)b * 16384 + 14336 + c4);
    out[(long)b * 512 + (i & 511)] =
        make_uint4(f2tf32(v.x), f2tf32(v.y), f2tf32(v.z), f2tf32(v.w));
}

// static [z][i=2048][n=512] fp32 -> stT [z][n][i=2048] tf32. 32x32 tiles.
__global__ void transpose_static_kernel(const float* __restrict__ in, float* __restrict__ out)
{
    __shared__ float tile[32][33];
    int z = blockIdx.z;
    int i0 = blockIdx.x * 32;
    int n0 = blockIdx.y * 32;
    const float* src = in + (long)z * 2048 * 512;
    float* dst = out + (long)z * 512 * 2048;
#pragma unroll
    for (int d = 0; d < 4; d++) {
        int row = i0 + threadIdx.y + d * 8;
        tile[threadIdx.y + d * 8][threadIdx.x] = src[(long)row * 512 + n0 + threadIdx.x];
    }
    __syncthreads();
#pragma unroll
    for (int d = 0; d < 4; d++) {
        int n = n0 + threadIdx.y + d * 8;
        dst[(long)n * 2048 + i0 + threadIdx.x] =
            __uint_as_float(f2tf32(tile[threadIdx.x][threadIdx.y + d * 8]));
    }
}

__global__ void concat_bias_kernel(const float* __restrict__ bk, const float* __restrict__ bv,
                                   float* __restrict__ bkv)
{
    int i = blockIdx.x * blockDim.x + threadIdx.x;
    if (i < 2048) bkv[i] = (i < 1024) ? bk[i] : bv[i - 1024];
}

// inv col norms from EkT rows: row = z*512+n, 1024 contiguous elems.
__global__ void ssqE_kernel(const float* __restrict__ EkT, float* __restrict__ invE)
{
    int row = blockIdx.x;
    const float* base = EkT + (long)row * 1024;
    int tid = threadIdx.x;
    float4 v = *(const float4*)&base[tid * 4];
    __shared__ float red[256];
    red[tid] = v.x * v.x + v.y * v.y + v.z * v.z + v.w * v.w;
    __syncthreads();
    for (int st = 128; st > 0; st >>= 1) {
        if (tid < st) red[tid] += red[tid + st];
        __syncthreads();
    }
    if (tid == 0) invE[row] = 1.f / fmaxf(sqrtf(red[0]), 1e-8f);
}

// normalize kv rows' first 1024 cols (k part) in place, write tf32 bits.
__global__ void norm_rows_kernel(float* __restrict__ KV)
{
    int b = blockIdx.x, tid = threadIdx.x;
    float* row = KV + (long)b * 2048;
    float4 v = *(float4*)&row[tid * 4];
    __shared__ float sred[256];
    sred[tid] = v.x * v.x + v.y * v.y + v.z * v.z + v.w * v.w;
    __syncthreads();
    for (int st = 128; st > 0; st >>= 1) {
        if (tid < st) sred[tid] += sred[tid + st];
        __syncthreads();
    }
    float inv = 1.f / fmaxf(sqrtf(sred[0]), 1e-8f);
    *(uint4*)&row[tid * 4] = make_uint4(f2tf32(v.x * inv), f2tf32(v.y * inv),
                                        f2tf32(v.z * inv), f2tf32(v.w * inv));
}

// scale by invE, softmax over 512, write tf32 bits in place. row = b*5+z.
__global__ void softmax_kernel(float* __restrict__ S, const float* __restrict__ invE)
{
    int row = blockIdx.x;
    int z = row % 5;
    float* base = S + (long)row * 512;
    int tid = threadIdx.x;
    float4 v = *(float4*)&base[tid * 4];
    float4 e = *(const float4*)&invE[z * 512 + tid * 4];
    v.x *= e.x; v.y *= e.y; v.z *= e.z; v.w *= e.w;
    __shared__ float sred[128];
    sred[tid] = fmaxf(fmaxf(v.x, v.y), fmaxf(v.z, v.w));
    __syncthreads();
    for (int st = 64; st > 0; st >>= 1) {
        if (tid < st) sred[tid] = fmaxf(sred[tid], sred[tid + st]);
        __syncthreads();
    }
    float m = sred[0];
    __syncthreads();
    v.x = expf(v.x - m); v.y = expf(v.y - m); v.z = expf(v.z - m); v.w = expf(v.w - m);
    sred[tid] = v.x + v.y + v.z + v.w;
    __syncthreads();
    for (int st = 64; st > 0; st >>= 1) {
        if (tid < st) sred[tid] += sred[tid + st];
        __syncthreads();
    }
    float inv = 1.f / sred[0];
    *(uint4*)&base[tid * 4] = make_uint4(f2tf32(v.x * inv), f2tf32(v.y * inv),
                                         f2tf32(v.z * inv), f2tf32(v.w * inv));
}

// Gate + concat + output GEMV per batch row. grid = B, 256 threads.
__global__ void final_kernel(const float* __restrict__ kv,
                             const float* __restrict__ fe,
                             const float* __restrict__ Ww,
                             const float* __restrict__ bw,
                             const float* __restrict__ Wout,
                             const float* __restrict__ bout,
                             float* __restrict__ out)
{
    const int b = blockIdx.x, tid = threadIdx.x;
    const long bc = (long)b * 1024;
    const long sz = (long)4096 * 1024;
    __shared__ float sred[256];
    __shared__ float s_fw[5];

    float acc[5] = {0.f, 0.f, 0.f, 0.f, 0.f};
    for (int c = tid; c < 1024; c += 256) {
        float wv = Ww[c];
#pragma unroll
        for (int kk = 0; kk < 5; kk++)
            acc[kk] = fmaf(wv, fe[sz * kk + bc + c], acc[kk]);
    }
#pragma unroll
    for (int kk = 0; kk < 5; kk++) {
        __syncthreads();
        sred[tid] = acc[kk];
        __syncthreads();
        for (int st = 128; st > 0; st >>= 1) {
            if (tid < st) sred[tid] += sred[tid + st];
            __syncthreads();
        }
        if (tid == 0) s_fw[kk] = 1.f / (1.f + expf(-(sred[0] + bw[0])));
    }
    __syncthreads();
    float fwl[5];
#pragma unroll
    for (int kk = 0; kk < 5; kk++) fwl[kk] = s_fw[kk];

    float oacc[5] = {0.f, 0.f, 0.f, 0.f, 0.f};
    for (int j = tid; j < 2048; j += 256) {
        float h;
        if (j < 1024) {
            h = kv[(long)b * 2048 + 1024 + j];   // v part
        } else {
            int c = j - 1024;
            float s = 0.f;
#pragma unroll
            for (int kk = 0; kk < 5; kk++)
                s = fmaf(fe[sz * kk + bc + c], fwl[kk], s);
            h = s;
        }
        h = fmaxf(h, 0.f);
#pragma unroll
        for (int kk = 0; kk < 5; kk++)
            oacc[kk] = fmaf(h, Wout[kk * 2048 + j], oacc[kk]);
    }
#pragma unroll
    for (int kk = 0; kk < 5; kk++) {
        __syncthreads();
        sred[tid] = oacc[kk];
        __syncthreads();
        for (int st = 128; st > 0; st >>= 1) {
            if (tid < st) sred[tid] += sred[tid + st];
            __syncthreads();
        }
        if (tid == 0) out[b * 5 + kk] = sred[0] + bout[kk];
    }
}

extern "C" void kernel_launch(void* const* d_in, const int* in_sizes, int n_in,
                              void* d_out, int out_size)
{
    const float* x    = (const float*)d_in[0];   // (4096, 8, 2048)
    const float* stat = (const float*)d_in[1];   // (5, 2048, 512)
    const float* Wk   = (const float*)d_in[2];   // (1024, 2048)
    const float* bk   = (const float*)d_in[3];
    const float* Wv   = (const float*)d_in[4];
    const float* bv   = (const float*)d_in[5];
    const float* WEk  = (const float*)d_in[6];
    const float* bEk  = (const float*)d_in[7];
    const float* WEv  = (const float*)d_in[8];
    const float* bEv  = (const float*)d_in[9];
    const float* Ww   = (const float*)d_in[10];
    const float* bw   = (const float*)d_in[11];
    const float* Wout = (const float*)d_in[12];  // (5, 2048)
    const float* bout = (const float*)d_in[13];
    float* out = (float*)d_out;                  // (4096, 5, 1)

    float *kv_, *EkT_, *Ev_, *sim_, *fe_, *invE_, *xl_, *wtf_, *stT_, *bkv_;
    cudaGetSymbolAddress((void**)&kv_,  g_kv);
    cudaGetSymbolAddress((void**)&EkT_, g_EkT);
    cudaGetSymbolAddress((void**)&Ev_,  g_Ev);
    cudaGetSymbolAddress((void**)&sim_, g_sim);
    cudaGetSymbolAddress((void**)&fe_,  g_fe);
    cudaGetSymbolAddress((void**)&invE_, g_invE);
    cudaGetSymbolAddress((void**)&xl_,  g_xl);
    cudaGetSymbolAddress((void**)&wtf_, g_wtf);
    cudaGetSymbolAddress((void**)&stT_, g_stT);
    cudaGetSymbolAddress((void**)&bkv_, g_bkv);

    constexpr int SMEM = 2 * 128 * 36 * 3 * 4;   // 110592 B
    cudaFuncSetAttribute(gemm_nt<0>, cudaFuncAttributeMaxDynamicSharedMemorySize, SMEM);
    cudaFuncSetAttribute(gemm_nt<1>, cudaFuncAttributeMaxDynamicSharedMemorySize, SMEM);

    // ---- preprocessing (tf32 conversion, transpose, gathers) ----
    gather_x_kernel<<<(4096 * 512) / 256, 256>>>(x, (uint4*)xl_);
    cvt4_kernel<<<2048, 256>>>((const float4*)Wk,  (uint4*)(wtf_ + 0L * 1024 * 2048), 1024 * 2048 / 4);
    cvt4_kernel<<<2048, 256>>>((const float4*)Wv,  (uint4*)(wtf_ + 1L * 1024 * 2048), 1024 * 2048 / 4);
    cvt4_kernel<<<2048, 256>>>((const float4*)WEk, (uint4*)(wtf_ + 2L * 1024 * 2048), 1024 * 2048 / 4);
    cvt4_kernel<<<2048, 256>>>((const float4*)WEv, (uint4*)(wtf_ + 3L * 1024 * 2048), 1024 * 2048 / 4);
    transpose_static_kernel<<<dim3(64, 16, 5), dim3(32, 8)>>>(stat, stT_);
    concat_bias_kernel<<<8, 256>>>(bk, bv, bkv_);

    // ---- [k|v] = x_last @ [Wk;Wv]^T + [bk;bv]  (NT, 4096x2048x2048) ----
    gemm_nt<0><<<dim3(16, 32, 1), 256, SMEM>>>(xl_, 2048, 0,
                                               wtf_, 2048, 0,
                                               kv_, 2048, 0, 2048, nullptr, bkv_);

    // ---- EkT[z][n][c] = staticT[z] @ WEk^T + bEk (NT, 512x1024x2048, tf32 out) ----
    gemm_nt<1><<<dim3(8, 4, 5), 256, SMEM>>>(stT_, 2048, (long)512 * 2048,
                                             wtf_ + 2L * 1024 * 2048, 2048, 0,
                                             EkT_, 1024, (long)512 * 1024, 2048, nullptr, bEk);

    // ---- Ev[z][c][n] = WEv @ staticT[z]^T + bEv (NT, 1024x512x2048, tf32 out) ----
    gemm_nt<1><<<dim3(4, 8, 5), 256, SMEM>>>(wtf_ + 3L * 1024 * 2048, 2048, 0,
                                             stT_, 2048, (long)512 * 2048,
                                             Ev_, 512, (long)1024 * 512, 2048, bEv, nullptr);

    ssqE_kernel<<<5 * 512, 256>>>(EkT_, invE_);
    norm_rows_kernel<<<4096, 256>>>(kv_);

    // ---- sim = kn @ EkT^T (NT, 4096x512x1024, z=5), fp32 out, ldc=2560 ----
    gemm_nt<0><<<dim3(4, 32, 5), 256, SMEM>>>(kv_, 2048, 0,
                                              EkT_, 1024, (long)512 * 1024,
                                              sim_, 5 * 512, 512, 1024, nullptr, nullptr);

    softmax_kernel<<<4096 * 5, 128>>>(sim_, invE_);

    // ---- fe = w @ Ev^T (NT, 4096x1024x512, z=5), fp32 out ----
    gemm_nt<0><<<dim3(8, 32, 5), 256, SMEM>>>(sim_, 5 * 512, 512,
                                              Ev_, 512, (long)1024 * 512,
                                              fe_, 1024, (long)4096 * 1024, 512, nullptr, nullptr);

    final_kernel<<<4096, 256>>>(kv_, fe_, Ww, bw, Wout, bout, out);
}

// round 7
// speedup vs baseline: 5.2529x; 1.5477x over previous
#include <cuda_runtime.h>
#include <cuda_fp16.h>
#include <math.h>

// Problem dims (fixed): B=4096, T=8, CH_IN=2048, C=1024, N=512, K=5, EPS=1e-8

__device__ float  g_kv [4096u * 2048u];          // [k | v] fp32 (GEMM out)
__device__ __half g_kn [4096u * 1024u];          // normalized k, fp16
__device__ __half g_EkT[5u * 512u * 1024u];      // EkT [z][n][c], fp16 (bias added)
__device__ __half g_Ev [5u * 1024u * 512u];      // Ev  [z][c][n], fp16 (bias added)
__device__ float  g_sim[4096u * 5u * 512u];      // sim fp32
__device__ __half g_wh [4096u * 5u * 512u];      // softmax weights fp16
__device__ float  g_fe [5u * 4096u * 1024u];     // feature_E fp32, [z][b][c]
__device__ float  g_invE[5u * 512u];             // 1/max(||Ek col||, eps)
__device__ __half g_xl [4096u * 2048u];          // x_last fp16
__device__ __half g_wtf[4u * 1024u * 2048u];     // Wk|Wv|WEk|WEv fp16
__device__ __half g_stT[5u * 512u * 2048u];      // static transposed [z][n][i] fp16
__device__ float  g_bkv[2048u];                  // bk | bv

#define DINLINE __device__ __forceinline__

DINLINE void mma_f16(float* c, const unsigned* a, const unsigned* b) {
    asm volatile(
        "mma.sync.aligned.m16n8k16.row.col.f32.f16.f16.f32 "
        "{%0,%1,%2,%3}, {%4,%5,%6,%7}, {%8,%9}, {%0,%1,%2,%3};"
        : "+f"(c[0]), "+f"(c[1]), "+f"(c[2]), "+f"(c[3])
        : "r"(a[0]), "r"(a[1]), "r"(a[2]), "r"(a[3]),
          "r"(b[0]), "r"(b[1]));
}

DINLINE void ldsm4(unsigned& r0, unsigned& r1, unsigned& r2, unsigned& r3, unsigned saddr) {
    asm volatile("ldmatrix.sync.aligned.m8n8.x4.shared.b16 {%0,%1,%2,%3}, [%4];"
                 : "=r"(r0), "=r"(r1), "=r"(r2), "=r"(r3) : "r"(saddr));
}

DINLINE void cp16(void* dst_smem, const void* src) {
    unsigned d = (unsigned)__cvta_generic_to_shared(dst_smem);
    asm volatile("cp.async.cg.shared.global [%0], [%1], 16;" :: "r"(d), "l"(src));
}
DINLINE void cp_commit() { asm volatile("cp.async.commit_group;"); }
DINLINE void cp_wait1()  { asm volatile("cp.async.wait_group 1;"); }
DINLINE void cp_wait0()  { asm volatile("cp.async.wait_group 0;"); }

// ---------------------------------------------------------------------------
// FP16 NT GEMM (C = A * B^T), fp32 accumulate. cp.async 3-stage + ldmatrix.
// 128x128x32 block tile, 256 threads (2x4 warps), warp = 64x32 m16n8k16.
// A, B fp16 K-major, SMEM rows stride 40 halves (80B: (20r)%32 spans all bank
// groups -> ldmatrix conflict-free; 80%16==0 -> cp16-aligned).
// HOUT=1: C is __half (bias added then rounded); HOUT=0: C is float.
// ---------------------------------------------------------------------------
template <int HOUT>
__global__ __launch_bounds__(256, 2)
void gemm_h(const __half* __restrict__ A, long lda, long sAz,
            const __half* __restrict__ Bm, long ldb, long sBz,
            void* __restrict__ Cv, long ldc, long sCz,
            int Kd,
            const float* __restrict__ bias_m,
            const float* __restrict__ bias_n)
{
    constexpr int ST = 40;                     // halves per smem row
    constexpr unsigned ABYTES = 128 * ST * 2;  // 10240
    constexpr unsigned STAGE  = 2 * ABYTES;    // 20480

    extern __shared__ char smem[];
    const unsigned shb = (unsigned)__cvta_generic_to_shared(smem);

    A  += (long)blockIdx.z * sAz;
    Bm += (long)blockIdx.z * sBz;
    const int m0 = blockIdx.y * 128;
    const int n0 = blockIdx.x * 128;
    const int tid  = threadIdx.x;
    const int lane = tid & 31;
    const int wid  = tid >> 5;
    const int g  = lane >> 2;
    const int tg = lane & 3;
    const int m_w = (wid & 1) * 64;
    const int n_w = (wid >> 1) * 32;

    // ldmatrix address roles (quad q = lane>>3, rr = lane&7)
    const int rr = lane & 7, q = lane >> 3;
    const int arow = ((q & 1) << 3) + rr;      // A: octets m0-7,m8-15,m0-7,m8-15
    const int acol = (q >> 1) << 3;            // halves: +0 / +8 (16B)
    const int brow = ((q >> 1) << 3) + rr;     // B: octets n0-7,n0-7,n8-15,n8-15
    const int bcol = (q & 1) << 3;

    unsigned aoff[4], boff[2];
#pragma unroll
    for (int mt = 0; mt < 4; mt++)
        aoff[mt] = ((m_w + mt * 16 + arow) * ST + acol) * 2;
#pragma unroll
    for (int nt2 = 0; nt2 < 2; nt2++)
        boff[nt2] = ABYTES + ((n_w + nt2 * 16 + brow) * ST + bcol) * 2;

    float acc[4][4][4];
#pragma unroll
    for (int i = 0; i < 4; i++)
#pragma unroll
        for (int j = 0; j < 4; j++)
#pragma unroll
            for (int p = 0; p < 4; p++) acc[i][j][p] = 0.f;

    auto issue = [&](int t) {
        const int kt = t << 5;                 // halves
        char* stg = smem + (unsigned)(t % 3) * STAGE;
#pragma unroll
        for (int i = 0; i < 2; i++) {          // A: 128 rows x 4 chunks of 16B
            int lin = i * 256 + tid;
            int r = lin >> 2, c = lin & 3;
            cp16(stg + r * 80 + c * 16, A + (long)(m0 + r) * lda + kt + c * 8);
        }
#pragma unroll
        for (int i = 0; i < 2; i++) {          // B: 128 rows x 4 chunks
            int lin = i * 256 + tid;
            int r = lin >> 2, c = lin & 3;
            cp16(stg + ABYTES + r * 80 + c * 16, Bm + (long)(n0 + r) * ldb + kt + c * 8);
        }
        cp_commit();
    };

    const int KT = Kd >> 5;
    issue(0);
    issue(1);

    for (int t = 0; t < KT; t++) {
        cp_wait1();
        __syncthreads();
        int tn = t + 2;
        if (tn < KT) issue(tn); else cp_commit();

        const unsigned stb = shb + (unsigned)(t % 3) * STAGE;
#pragma unroll
        for (int s = 0; s < 2; s++) {          // two k16 steps per chunk
            const unsigned kb = s * 32;        // 16 halves = 32B
            unsigned af[4][4], bf[4][2];
#pragma unroll
            for (int mt = 0; mt < 4; mt++)
                ldsm4(af[mt][0], af[mt][1], af[mt][2], af[mt][3], stb + aoff[mt] + kb);
#pragma unroll
            for (int nt2 = 0; nt2 < 2; nt2++)
                ldsm4(bf[2 * nt2][0], bf[2 * nt2][1],
                      bf[2 * nt2 + 1][0], bf[2 * nt2 + 1][1], stb + boff[nt2] + kb);
#pragma unroll
            for (int mt = 0; mt < 4; mt++)
#pragma unroll
                for (int nt = 0; nt < 4; nt++)
                    mma_f16(acc[mt][nt], af[mt], bf[nt]);
        }
    }
    cp_wait0();

    // Epilogue: c0:(g,2tg) c1:(g,2tg+1) c2:(g+8,2tg) c3:(g+8,2tg+1)
#pragma unroll
    for (int mt = 0; mt < 4; mt++) {
        int r0 = m0 + m_w + mt * 16 + g;
        float bm0 = bias_m ? bias_m[r0]     : 0.f;
        float bm1 = bias_m ? bias_m[r0 + 8] : 0.f;
#pragma unroll
        for (int nt = 0; nt < 4; nt++) {
            int cc = n0 + n_w + nt * 8 + 2 * tg;
            float bn0 = bias_n ? bias_n[cc]     : 0.f;
            float bn1 = bias_n ? bias_n[cc + 1] : 0.f;
            const float* c = acc[mt][nt];
            float v00 = c[0] + bm0 + bn0, v01 = c[1] + bm0 + bn1;
            float v10 = c[2] + bm1 + bn0, v11 = c[3] + bm1 + bn1;
            if (HOUT) {
                __half* Cm = (__half*)Cv + (long)blockIdx.z * sCz;
                *(__half2*)(Cm + (long)r0 * ldc + cc)       = __floats2half2_rn(v00, v01);
                *(__half2*)(Cm + (long)(r0 + 8) * ldc + cc) = __floats2half2_rn(v10, v11);
            } else {
                float* Cm = (float*)Cv + (long)blockIdx.z * sCz;
                *(float2*)(Cm + (long)r0 * ldc + cc)       = make_float2(v00, v01);
                *(float2*)(Cm + (long)(r0 + 8) * ldc + cc) = make_float2(v10, v11);
            }
        }
    }
}

// --- pre-processing ---------------------------------------------------------
__global__ void cvt_h_kernel(const float4* __restrict__ in, __half2* __restrict__ out, int n4)
{
    int i = blockIdx.x * blockDim.x + threadIdx.x;
    if (i < n4) {
        float4 v = in[i];
        out[2 * i]     = __floats2half2_rn(v.x, v.y);
        out[2 * i + 1] = __floats2half2_rn(v.z, v.w);
    }
}

__global__ void gather_x_kernel(const float* __restrict__ x, __half2* __restrict__ out)
{
    int i = blockIdx.x * blockDim.x + threadIdx.x;    // float4 index over 4096*512
    int b  = i >> 9;
    int c4 = (i & 511) * 4;
    float4 v = *(const float4*)(x + (long)b * 16384 + 14336 + c4);
    out[(long)b * 1024 + (i & 511) * 2]     = __floats2half2_rn(v.x, v.y);
    out[(long)b * 1024 + (i & 511) * 2 + 1] = __floats2half2_rn(v.z, v.w);
}

// static [z][i=2048][n=512] fp32 -> stT [z][n][i=2048] fp16. 32x32 tiles.
__global__ void transpose_static_kernel(const float* __restrict__ in, __half* __restrict__ out)
{
    __shared__ float tile[32][33];
    int z = blockIdx.z;
    int i0 = blockIdx.x * 32;
    int n0 = blockIdx.y * 32;
    const float* src = in + (long)z * 2048 * 512;
    __half* dst = out + (long)z * 512 * 2048;
#pragma unroll
    for (int d = 0; d < 4; d++) {
        int row = i0 + threadIdx.y + d * 8;
        tile[threadIdx.y + d * 8][threadIdx.x] = src[(long)row * 512 + n0 + threadIdx.x];
    }
    __syncthreads();
#pragma unroll
    for (int d = 0; d < 4; d++) {
        int n = n0 + threadIdx.y + d * 8;
        dst[(long)n * 2048 + i0 + threadIdx.x] =
            __float2half_rn(tile[threadIdx.x][threadIdx.y + d * 8]);
    }
}

__global__ void concat_bias_kernel(const float* __restrict__ bk, const float* __restrict__ bv,
                                   float* __restrict__ bkv)
{
    int i = blockIdx.x * blockDim.x + threadIdx.x;
    if (i < 2048) bkv[i] = (i < 1024) ? bk[i] : bv[i - 1024];
}

// inv col norms from fp16 EkT rows: row = z*512+n, 1024 contiguous halves.
__global__ void ssqE_kernel(const __half* __restrict__ EkT, float* __restrict__ invE)
{
    int row = blockIdx.x;
    const __half2* base = (const __half2*)(EkT + (long)row * 1024);
    int tid = threadIdx.x;
    float2 a = __half22float2(base[tid * 2]);
    float2 b = __half22float2(base[tid * 2 + 1]);
    __shared__ float red[256];
    red[tid] = a.x * a.x + a.y * a.y + b.x * b.x + b.y * b.y;
    __syncthreads();
    for (int st = 128; st > 0; st >>= 1) {
        if (tid < st) red[tid] += red[tid + st];
        __syncthreads();
    }
    if (tid == 0) invE[row] = 1.f / fmaxf(sqrtf(red[0]), 1e-8f);
}

// normalize k (first 1024 cols of kv row), write fp16 kn. grid=B, 256 thr.
__global__ void norm_rows_kernel(const float* __restrict__ KV, __half* __restrict__ KN)
{
    int b = blockIdx.x, tid = threadIdx.x;
    const float* row = KV + (long)b * 2048;
    float4 v = *(const float4*)&row[tid * 4];
    __shared__ float sred[256];
    sred[tid] = v.x * v.x + v.y * v.y + v.z * v.z + v.w * v.w;
    __syncthreads();
    for (int st = 128; st > 0; st >>= 1) {
        if (tid < st) sred[tid] += sred[tid + st];
        __syncthreads();
    }
    float inv = 1.f / fmaxf(sqrtf(sred[0]), 1e-8f);
    __half2* o = (__half2*)(KN + (long)b * 1024);
    o[tid * 2]     = __floats2half2_rn(v.x * inv, v.y * inv);
    o[tid * 2 + 1] = __floats2half2_rn(v.z * inv, v.w * inv);
}

// scale by invE, softmax over 512, write fp16 weights. row = b*5+z.
__global__ void softmax_kernel(const float* __restrict__ S, const float* __restrict__ invE,
                               __half* __restrict__ W)
{
    int row = blockIdx.x;
    int z = row % 5;
    const float* base = S + (long)row * 512;
    int tid = threadIdx.x;
    float4 v = *(const float4*)&base[tid * 4];
    float4 e = *(const float4*)&invE[z * 512 + tid * 4];
    v.x *= e.x; v.y *= e.y; v.z *= e.z; v.w *= e.w;
    __shared__ float sred[128];
    sred[tid] = fmaxf(fmaxf(v.x, v.y), fmaxf(v.z, v.w));
    __syncthreads();
    for (int st = 64; st > 0; st >>= 1) {
        if (tid < st) sred[tid] = fmaxf(sred[tid], sred[tid + st]);
        __syncthreads();
    }
    float m = sred[0];
    __syncthreads();
    v.x = expf(v.x - m); v.y = expf(v.y - m); v.z = expf(v.z - m); v.w = expf(v.w - m);
    sred[tid] = v.x + v.y + v.z + v.w;
    __syncthreads();
    for (int st = 64; st > 0; st >>= 1) {
        if (tid < st) sred[tid] += sred[tid + st];
        __syncthreads();
    }
    float inv = 1.f / sred[0];
    __half2* o = (__half2*)(W + (long)row * 512);
    o[tid * 2]     = __floats2half2_rn(v.x * inv, v.y * inv);
    o[tid * 2 + 1] = __floats2half2_rn(v.z * inv, v.w * inv);
}

// Gate + concat + output GEMV per batch row. grid = B, 256 threads.
__global__ void final_kernel(const float* __restrict__ kv,
                             const float* __restrict__ fe,
                             const float* __restrict__ Ww,
                             const float* __restrict__ bw,
                             const float* __restrict__ Wout,
                             const float* __restrict__ bout,
                             float* __restrict__ out)
{
    const int b = blockIdx.x, tid = threadIdx.x;
    const long bc = (long)b * 1024;
    const long sz = (long)4096 * 1024;
    __shared__ float sred[256];
    __shared__ float s_fw[5];

    float acc[5] = {0.f, 0.f, 0.f, 0.f, 0.f};
    for (int c = tid; c < 1024; c += 256) {
        float wv = Ww[c];
#pragma unroll
        for (int kk = 0; kk < 5; kk++)
            acc[kk] = fmaf(wv, fe[sz * kk + bc + c], acc[kk]);
    }
#pragma unroll
    for (int kk = 0; kk < 5; kk++) {
        __syncthreads();
        sred[tid] = acc[kk];
        __syncthreads();
        for (int st = 128; st > 0; st >>= 1) {
            if (tid < st) sred[tid] += sred[tid + st];
            __syncthreads();
        }
        if (tid == 0) s_fw[kk] = 1.f / (1.f + expf(-(sred[0] + bw[0])));
    }
    __syncthreads();
    float fwl[5];
#pragma unroll
    for (int kk = 0; kk < 5; kk++) fwl[kk] = s_fw[kk];

    float oacc[5] = {0.f, 0.f, 0.f, 0.f, 0.f};
    for (int j = tid; j < 2048; j += 256) {
        float h;
        if (j < 1024) {
            h = kv[(long)b * 2048 + 1024 + j];   // v part
        } else {
            int c = j - 1024;
            float s = 0.f;
#pragma unroll
            for (int kk = 0; kk < 5; kk++)
                s = fmaf(fe[sz * kk + bc + c], fwl[kk], s);
            h = s;
        }
        h = fmaxf(h, 0.f);
#pragma unroll
        for (int kk = 0; kk < 5; kk++)
            oacc[kk] = fmaf(h, Wout[kk * 2048 + j], oacc[kk]);
    }
#pragma unroll
    for (int kk = 0; kk < 5; kk++) {
        __syncthreads();
        sred[tid] = oacc[kk];
        __syncthreads();
        for (int st = 128; st > 0; st >>= 1) {
            if (tid < st) sred[tid] += sred[tid + st];
            __syncthreads();
        }
        if (tid == 0) out[b * 5 + kk] = sred[0] + bout[kk];
    }
}

extern "C" void kernel_launch(void* const* d_in, const int* in_sizes, int n_in,
                              void* d_out, int out_size)
{
    const float* x    = (const float*)d_in[0];   // (4096, 8, 2048)
    const float* stat = (const float*)d_in[1];   // (5, 2048, 512)
    const float* Wk   = (const float*)d_in[2];   // (1024, 2048)
    const float* bk   = (const float*)d_in[3];
    const float* Wv   = (const float*)d_in[4];
    const float* bv   = (const float*)d_in[5];
    const float* WEk  = (const float*)d_in[6];
    const float* bEk  = (const float*)d_in[7];
    const float* WEv  = (const float*)d_in[8];
    const float* bEv  = (const float*)d_in[9];
    const float* Ww   = (const float*)d_in[10];
    const float* bw   = (const float*)d_in[11];
    const float* Wout = (const float*)d_in[12];  // (5, 2048)
    const float* bout = (const float*)d_in[13];
    float* out = (float*)d_out;                  // (4096, 5, 1)

    float *kv_, *sim_, *fe_, *invE_, *bkv_;
    __half *kn_, *EkT_, *Ev_, *wh_, *xl_, *wtf_, *stT_;
    cudaGetSymbolAddress((void**)&kv_,  g_kv);
    cudaGetSymbolAddress((void**)&kn_,  g_kn);
    cudaGetSymbolAddress((void**)&EkT_, g_EkT);
    cudaGetSymbolAddress((void**)&Ev_,  g_Ev);
    cudaGetSymbolAddress((void**)&sim_, g_sim);
    cudaGetSymbolAddress((void**)&wh_,  g_wh);
    cudaGetSymbolAddress((void**)&fe_,  g_fe);
    cudaGetSymbolAddress((void**)&invE_, g_invE);
    cudaGetSymbolAddress((void**)&xl_,  g_xl);
    cudaGetSymbolAddress((void**)&wtf_, g_wtf);
    cudaGetSymbolAddress((void**)&stT_, g_stT);
    cudaGetSymbolAddress((void**)&bkv_, g_bkv);

    constexpr int SMEM = 3 * 2 * 128 * 40 * 2;   // 61440 B
    cudaFuncSetAttribute(gemm_h<0>, cudaFuncAttributeMaxDynamicSharedMemorySize, SMEM);
    cudaFuncSetAttribute(gemm_h<1>, cudaFuncAttributeMaxDynamicSharedMemorySize, SMEM);

    // ---- preprocessing (fp16 conversion, transpose, gathers) ----
    gather_x_kernel<<<(4096 * 512) / 256, 256>>>(x, (__half2*)xl_);
    cvt_h_kernel<<<2048, 256>>>((const float4*)Wk,  (__half2*)(wtf_ + 0L * 1024 * 2048), 1024 * 2048 / 4);
    cvt_h_kernel<<<2048, 256>>>((const float4*)Wv,  (__half2*)(wtf_ + 1L * 1024 * 2048), 1024 * 2048 / 4);
    cvt_h_kernel<<<2048, 256>>>((const float4*)WEk, (__half2*)(wtf_ + 2L * 1024 * 2048), 1024 * 2048 / 4);
    cvt_h_kernel<<<2048, 256>>>((const float4*)WEv, (__half2*)(wtf_ + 3L * 1024 * 2048), 1024 * 2048 / 4);
    transpose_static_kernel<<<dim3(64, 16, 5), dim3(32, 8)>>>(stat, stT_);
    concat_bias_kernel<<<8, 256>>>(bk, bv, bkv_);

    // ---- [k|v] = x_last @ [Wk;Wv]^T + [bk;bv]  (NT, 4096x2048x2048, fp32 out) ----
    gemm_h<0><<<dim3(16, 32, 1), 256, SMEM>>>(xl_, 2048, 0,
                                              wtf_, 2048, 0,
                                              kv_, 2048, 0, 2048, nullptr, bkv_);

    // ---- EkT[z][n][c] = staticT[z] @ WEk^T + bEk (NT, 512x1024x2048, fp16 out) ----
    gemm_h<1><<<dim3(8, 4, 5), 256, SMEM>>>(stT_, 2048, (long)512 * 2048,
                                            wtf_ + 2L * 1024 * 2048, 2048, 0,
                                            EkT_, 1024, (long)512 * 1024, 2048, nullptr, bEk);

    // ---- Ev[z][c][n] = WEv @ staticT[z]^T + bEv (NT, 1024x512x2048, fp16 out) ----
    gemm_h<1><<<dim3(4, 8, 5), 256, SMEM>>>(wtf_ + 3L * 1024 * 2048, 2048, 0,
                                            stT_, 2048, (long)512 * 2048,
                                            Ev_, 512, (long)1024 * 512, 2048, bEv, nullptr);

    ssqE_kernel<<<5 * 512, 256>>>(EkT_, invE_);
    norm_rows_kernel<<<4096, 256>>>(kv_, kn_);

    // ---- sim = kn @ EkT^T (NT, 4096x512x1024, z=5), fp32 out, ldc=2560 ----
    gemm_h<0><<<dim3(4, 32, 5), 256, SMEM>>>(kn_, 1024, 0,
                                             EkT_, 1024, (long)512 * 1024,
                                             sim_, 5 * 512, 512, 1024, nullptr, nullptr);

    softmax_kernel<<<4096 * 5, 128>>>(sim_, invE_, wh_);

    // ---- fe = w @ Ev^T (NT, 4096x1024x512, z=5), fp32 out ----
    gemm_h<0><<<dim3(8, 32, 5), 256, SMEM>>>(wh_, 5 * 512, 512,
                                             Ev_, 512, (long)1024 * 512,
                                             fe_, 1024, (long)4096 * 1024, 512, nullptr, nullptr);

    final_kernel<<<4096, 256>>>(kv_, fe_, Ww, bw, Wout, bout, out);
}

// round 8
// speedup vs baseline: 5.3768x; 1.0236x over previous
#include <cuda_runtime.h>
#include <cuda_fp16.h>
#include <math.h>

// Problem dims (fixed): B=4096, T=8, CH_IN=2048, C=1024, N=512, K=5, EPS=1e-8

__device__ float  g_kv [4096u * 2048u];          // [k | v] fp32 (GEMM out)
__device__ __half g_kn [4096u * 1024u];          // normalized k, fp16
__device__ __half g_EkT[5u * 512u * 1024u];      // EkT [z][n][c], fp16 (bias added)
__device__ __half g_Ev [5u * 1024u * 512u];      // Ev  [z][c][n], fp16 (bias added)
__device__ float  g_sim[4096u * 5u * 512u];      // sim fp32
__device__ __half g_wh [4096u * 5u * 512u];      // softmax weights fp16
__device__ __half g_feh[5u * 4096u * 1024u];     // feature_E fp16, [z][b][c]
__device__ float  g_invE[5u * 512u];             // 1/max(||Ek col||, eps)
__device__ __half g_xl [4096u * 2048u];          // x_last fp16
__device__ __half g_wtf[4u * 1024u * 2048u];     // Wk|Wv|WEk|WEv fp16
__device__ __half g_stT[5u * 512u * 2048u];      // static transposed [z][n][i] fp16
__device__ float  g_bkv[2048u];                  // bk | bv

#define DINLINE __device__ __forceinline__

DINLINE void mma_f16(float* c, const unsigned* a, const unsigned* b) {
    asm volatile(
        "mma.sync.aligned.m16n8k16.row.col.f32.f16.f16.f32 "
        "{%0,%1,%2,%3}, {%4,%5,%6,%7}, {%8,%9}, {%0,%1,%2,%3};"
        : "+f"(c[0]), "+f"(c[1]), "+f"(c[2]), "+f"(c[3])
        : "r"(a[0]), "r"(a[1]), "r"(a[2]), "r"(a[3]),
          "r"(b[0]), "r"(b[1]));
}

DINLINE void ldsm4(unsigned& r0, unsigned& r1, unsigned& r2, unsigned& r3, unsigned saddr) {
    asm volatile("ldmatrix.sync.aligned.m8n8.x4.shared.b16 {%0,%1,%2,%3}, [%4];"
                 : "=r"(r0), "=r"(r1), "=r"(r2), "=r"(r3) : "r"(saddr));
}

DINLINE void cp16(void* dst_smem, const void* src) {
    unsigned d = (unsigned)__cvta_generic_to_shared(dst_smem);
    asm volatile("cp.async.cg.shared.global [%0], [%1], 16;" :: "r"(d), "l"(src));
}
DINLINE void cp_commit() { asm volatile("cp.async.commit_group;"); }
DINLINE void cp_wait2()  { asm volatile("cp.async.wait_group 2;"); }
DINLINE void cp_wait0()  { asm volatile("cp.async.wait_group 0;"); }

// ---------------------------------------------------------------------------
// FP16 NT GEMM (C = A * B^T), fp32 accumulate. cp.async 4-stage + ldmatrix.
// 128x128x32 block tile, 256 threads (2x4 warps), warp = 64x32 m16n8k16.
// SMEM rows stride 40 halves (80B) -> ldmatrix conflict-free, cp16-aligned.
// HOUT=1: C is __half (bias added then rounded); HOUT=0: C is float.
// ---------------------------------------------------------------------------
template <int HOUT>
__global__ __launch_bounds__(256, 2)
void gemm_h(const __half* __restrict__ A, long lda, long sAz,
            const __half* __restrict__ Bm, long ldb, long sBz,
            void* __restrict__ Cv, long ldc, long sCz,
            int Kd,
            const float* __restrict__ bias_m,
            const float* __restrict__ bias_n)
{
    constexpr int ST = 40;                     // halves per smem row
    constexpr unsigned ABYTES = 128 * ST * 2;  // 10240
    constexpr unsigned STAGE  = 2 * ABYTES;    // 20480

    extern __shared__ char smem[];
    const unsigned shb = (unsigned)__cvta_generic_to_shared(smem);

    A  += (long)blockIdx.z * sAz;
    Bm += (long)blockIdx.z * sBz;
    const int m0 = blockIdx.y * 128;
    const int n0 = blockIdx.x * 128;
    const int tid  = threadIdx.x;
    const int lane = tid & 31;
    const int wid  = tid >> 5;
    const int g  = lane >> 2;
    const int tg = lane & 3;
    const int m_w = (wid & 1) * 64;
    const int n_w = (wid >> 1) * 32;

    // ldmatrix address roles (quad q = lane>>3, rr = lane&7)
    const int rr = lane & 7, q = lane >> 3;
    const int arow = ((q & 1) << 3) + rr;
    const int acol = (q >> 1) << 3;            // halves: +0 / +8 (16B)
    const int brow = ((q >> 1) << 3) + rr;
    const int bcol = (q & 1) << 3;

    unsigned aoff[4], boff[2];
#pragma unroll
    for (int mt = 0; mt < 4; mt++)
        aoff[mt] = ((m_w + mt * 16 + arow) * ST + acol) * 2;
#pragma unroll
    for (int nt2 = 0; nt2 < 2; nt2++)
        boff[nt2] = ABYTES + ((n_w + nt2 * 16 + brow) * ST + bcol) * 2;

    float acc[4][4][4];
#pragma unroll
    for (int i = 0; i < 4; i++)
#pragma unroll
        for (int j = 0; j < 4; j++)
#pragma unroll
            for (int p = 0; p < 4; p++) acc[i][j][p] = 0.f;

    auto issue = [&](int t) {
        const int kt = t << 5;                 // halves
        char* stg = smem + (unsigned)(t & 3) * STAGE;
#pragma unroll
        for (int i = 0; i < 2; i++) {          // A: 128 rows x 4 chunks of 16B
            int lin = i * 256 + tid;
            int r = lin >> 2, c = lin & 3;
            cp16(stg + r * 80 + c * 16, A + (long)(m0 + r) * lda + kt + c * 8);
        }
#pragma unroll
        for (int i = 0; i < 2; i++) {          // B: 128 rows x 4 chunks
            int lin = i * 256 + tid;
            int r = lin >> 2, c = lin & 3;
            cp16(stg + ABYTES + r * 80 + c * 16, Bm + (long)(n0 + r) * ldb + kt + c * 8);
        }
        cp_commit();
    };

    const int KT = Kd >> 5;
    issue(0);
    issue(1);
    issue(2);

    for (int t = 0; t < KT; t++) {
        cp_wait2();            // chunk t landed; t+1, t+2 may be in flight
        __syncthreads();
        int tn = t + 3;
        if (tn < KT) issue(tn); else cp_commit();   // keep group arithmetic valid

        const unsigned stb = shb + (unsigned)(t & 3) * STAGE;
#pragma unroll
        for (int s = 0; s < 2; s++) {          // two k16 steps per chunk
            const unsigned kb = s * 32;        // 16 halves = 32B
            unsigned af[4][4], bf[4][2];
#pragma unroll
            for (int mt = 0; mt < 4; mt++)
                ldsm4(af[mt][0], af[mt][1], af[mt][2], af[mt][3], stb + aoff[mt] + kb);
#pragma unroll
            for (int nt2 = 0; nt2 < 2; nt2++)
                ldsm4(bf[2 * nt2][0], bf[2 * nt2][1],
                      bf[2 * nt2 + 1][0], bf[2 * nt2 + 1][1], stb + boff[nt2] + kb);
#pragma unroll
            for (int mt = 0; mt < 4; mt++)
#pragma unroll
                for (int nt = 0; nt < 4; nt++)
                    mma_f16(acc[mt][nt], af[mt], bf[nt]);
        }
    }
    cp_wait0();

    // Epilogue: c0:(g,2tg) c1:(g,2tg+1) c2:(g+8,2tg) c3:(g+8,2tg+1)
#pragma unroll
    for (int mt = 0; mt < 4; mt++) {
        int r0 = m0 + m_w + mt * 16 + g;
        float bm0 = bias_m ? bias_m[r0]     : 0.f;
        float bm1 = bias_m ? bias_m[r0 + 8] : 0.f;
#pragma unroll
        for (int nt = 0; nt < 4; nt++) {
            int cc = n0 + n_w + nt * 8 + 2 * tg;
            float bn0 = bias_n ? bias_n[cc]     : 0.f;
            float bn1 = bias_n ? bias_n[cc + 1] : 0.f;
            const float* c = acc[mt][nt];
            float v00 = c[0] + bm0 + bn0, v01 = c[1] + bm0 + bn1;
            float v10 = c[2] + bm1 + bn0, v11 = c[3] + bm1 + bn1;
            if (HOUT) {
                __half* Cm = (__half*)Cv + (long)blockIdx.z * sCz;
                *(__half2*)(Cm + (long)r0 * ldc + cc)       = __floats2half2_rn(v00, v01);
                *(__half2*)(Cm + (long)(r0 + 8) * ldc + cc) = __floats2half2_rn(v10, v11);
            } else {
                float* Cm = (float*)Cv + (long)blockIdx.z * sCz;
                *(float2*)(Cm + (long)r0 * ldc + cc)       = make_float2(v00, v01);
                *(float2*)(Cm + (long)(r0 + 8) * ldc + cc) = make_float2(v10, v11);
            }
        }
    }
}

// --- pre-processing ---------------------------------------------------------
__global__ void cvt_h_kernel(const float4* __restrict__ in, __half2* __restrict__ out, int n4)
{
    int i = blockIdx.x * blockDim.x + threadIdx.x;
    if (i < n4) {
        float4 v = in[i];
        out[2 * i]     = __floats2half2_rn(v.x, v.y);
        out[2 * i + 1] = __floats2half2_rn(v.z, v.w);
    }
}

__global__ void gather_x_kernel(const float* __restrict__ x, __half2* __restrict__ out)
{
    int i = blockIdx.x * blockDim.x + threadIdx.x;    // float4 index over 4096*512
    int b  = i >> 9;
    int c4 = (i & 511) * 4;
    float4 v = *(const float4*)(x + (long)b * 16384 + 14336 + c4);
    out[(long)b * 1024 + (i & 511) * 2]     = __floats2half2_rn(v.x, v.y);
    out[(long)b * 1024 + (i & 511) * 2 + 1] = __floats2half2_rn(v.z, v.w);
}

// static [z][i=2048][n=512] fp32 -> stT [z][n][i=2048] fp16. 32x32 tiles.
__global__ void transpose_static_kernel(const float* __restrict__ in, __half* __restrict__ out)
{
    __shared__ float tile[32][33];
    int z = blockIdx.z;
    int i0 = blockIdx.x * 32;
    int n0 = blockIdx.y * 32;
    const float* src = in + (long)z * 2048 * 512;
    __half* dst = out + (long)z * 512 * 2048;
#pragma unroll
    for (int d = 0; d < 4; d++) {
        int row = i0 + threadIdx.y + d * 8;
        tile[threadIdx.y + d * 8][threadIdx.x] = src[(long)row * 512 + n0 + threadIdx.x];
    }
    __syncthreads();
#pragma unroll
    for (int d = 0; d < 4; d++) {
        int n = n0 + threadIdx.y + d * 8;
        dst[(long)n * 2048 + i0 + threadIdx.x] =
            __float2half_rn(tile[threadIdx.x][threadIdx.y + d * 8]);
    }
}

__global__ void concat_bias_kernel(const float* __restrict__ bk, const float* __restrict__ bv,
                                   float* __restrict__ bkv)
{
    int i = blockIdx.x * blockDim.x + threadIdx.x;
    if (i < 2048) bkv[i] = (i < 1024) ? bk[i] : bv[i - 1024];
}

// inv col norms from fp16 EkT rows: row = z*512+n, 1024 contiguous halves.
__global__ void ssqE_kernel(const __half* __restrict__ EkT, float* __restrict__ invE)
{
    int row = blockIdx.x;
    const __half2* base = (const __half2*)(EkT + (long)row * 1024);
    int tid = threadIdx.x;
    float2 a = __half22float2(base[tid * 2]);
    float2 b = __half22float2(base[tid * 2 + 1]);
    __shared__ float red[256];
    red[tid] = a.x * a.x + a.y * a.y + b.x * b.x + b.y * b.y;
    __syncthreads();
    for (int st = 128; st > 0; st >>= 1) {
        if (tid < st) red[tid] += red[tid + st];
        __syncthreads();
    }
    if (tid == 0) invE[row] = 1.f / fmaxf(sqrtf(red[0]), 1e-8f);
}

// normalize k (first 1024 cols of kv row), write fp16 kn. grid=B, 256 thr.
__global__ void norm_rows_kernel(const float* __restrict__ KV, __half* __restrict__ KN)
{
    int b = blockIdx.x, tid = threadIdx.x;
    const float* row = KV + (long)b * 2048;
    float4 v = *(const float4*)&row[tid * 4];
    __shared__ float sred[256];
    sred[tid] = v.x * v.x + v.y * v.y + v.z * v.z + v.w * v.w;
    __syncthreads();
    for (int st = 128; st > 0; st >>= 1) {
        if (tid < st) sred[tid] += sred[tid + st];
        __syncthreads();
    }
    float inv = 1.f / fmaxf(sqrtf(sred[0]), 1e-8f);
    __half2* o = (__half2*)(KN + (long)b * 1024);
    o[tid * 2]     = __floats2half2_rn(v.x * inv, v.y * inv);
    o[tid * 2 + 1] = __floats2half2_rn(v.z * inv, v.w * inv);
}

// scale by invE, softmax over 512, write fp16 weights. row = b*5+z.
__global__ void softmax_kernel(const float* __restrict__ S, const float* __restrict__ invE,
                               __half* __restrict__ W)
{
    int row = blockIdx.x;
    int z = row % 5;
    const float* base = S + (long)row * 512;
    int tid = threadIdx.x;
    float4 v = *(const float4*)&base[tid * 4];
    float4 e = *(const float4*)&invE[z * 512 + tid * 4];
    v.x *= e.x; v.y *= e.y; v.z *= e.z; v.w *= e.w;
    __shared__ float sred[128];
    sred[tid] = fmaxf(fmaxf(v.x, v.y), fmaxf(v.z, v.w));
    __syncthreads();
    for (int st = 64; st > 0; st >>= 1) {
        if (tid < st) sred[tid] = fmaxf(sred[tid], sred[tid + st]);
        __syncthreads();
    }
    float m = sred[0];
    __syncthreads();
    v.x = expf(v.x - m); v.y = expf(v.y - m); v.z = expf(v.z - m); v.w = expf(v.w - m);
    sred[tid] = v.x + v.y + v.z + v.w;
    __syncthreads();
    for (int st = 64; st > 0; st >>= 1) {
        if (tid < st) sred[tid] += sred[tid + st];
        __syncthreads();
    }
    float inv = 1.f / sred[0];
    __half2* o = (__half2*)(W + (long)row * 512);
    o[tid * 2]     = __floats2half2_rn(v.x * inv, v.y * inv);
    o[tid * 2 + 1] = __floats2half2_rn(v.z * inv, v.w * inv);
}

// ---------------------------------------------------------------------------
// Final stage: gate + concat + output GEMV. grid = B/16, 256 threads.
// Thread t owns c-slice [4t, 4t+4). Ww/Wout slices live in registers across
// all 16 batch rows. Reductions: warp shfl + one 8-wide smem stage.
// ---------------------------------------------------------------------------
__global__ __launch_bounds__(256)
void final_kernel(const float* __restrict__ kv,
                  const __half* __restrict__ feh,
                  const float* __restrict__ Ww,
                  const float* __restrict__ bw,
                  const float* __restrict__ Wout,
                  const float* __restrict__ bout,
                  float* __restrict__ out)
{
    const int tid = threadIdx.x, lane = tid & 31, wid = tid >> 5;
    const int c0 = tid * 4;
    const long sz = (long)4096 * 1024;

    // Register-resident weight slices (shared across 16 rows)
    float ww[4];
    float wv[5][4], wf[5][4];
    *(float4*)ww = *(const float4*)&Ww[c0];
#pragma unroll
    for (int kk = 0; kk < 5; kk++) {
        *(float4*)wv[kk] = *(const float4*)&Wout[kk * 2048 + c0];
        *(float4*)wf[kk] = *(const float4*)&Wout[kk * 2048 + 1024 + c0];
    }
    const float bwv = bw[0];

    __shared__ float wred[5][8];
    __shared__ float s_fw[5];

    for (int bi = 0; bi < 16; bi++) {
        const int b = blockIdx.x * 16 + bi;
        const long bc = (long)b * 1024 + c0;

        // load fe[k][b][c-slice] and v[b][c-slice]
        float fe[5][4];
#pragma unroll
        for (int kk = 0; kk < 5; kk++) {
            __half2 h0 = *(const __half2*)(feh + sz * kk + bc);
            __half2 h1 = *(const __half2*)(feh + sz * kk + bc + 2);
            float2 f0 = __half22float2(h0), f1 = __half22float2(h1);
            fe[kk][0] = f0.x; fe[kk][1] = f0.y; fe[kk][2] = f1.x; fe[kk][3] = f1.y;
        }
        float4 vv = *(const float4*)(kv + (long)b * 2048 + 1024 + c0);

        // fw[k] = sigmoid(sum_c Ww[c]*fe[k][c] + bw)
        float acc[5];
#pragma unroll
        for (int kk = 0; kk < 5; kk++) {
            float s = fe[kk][0] * ww[0] + fe[kk][1] * ww[1]
                    + fe[kk][2] * ww[2] + fe[kk][3] * ww[3];
#pragma unroll
            for (int o = 16; o > 0; o >>= 1) s += __shfl_xor_sync(0xFFFFFFFFu, s, o);
            acc[kk] = s;
        }
        if (lane == 0) {
#pragma unroll
            for (int kk = 0; kk < 5; kk++) wred[kk][wid] = acc[kk];
        }
        __syncthreads();
        if (tid < 5) {
            float s = 0.f;
#pragma unroll
            for (int w = 0; w < 8; w++) s += wred[tid][w];
            s_fw[tid] = 1.f / (1.f + expf(-(s + bwv)));
        }
        __syncthreads();
        float fwl[5];
#pragma unroll
        for (int kk = 0; kk < 5; kk++) fwl[kk] = s_fw[kk];

        // h = [relu(v) | relu(fE)]; oacc[k2] = sum_j h[j]*Wout[k2][j]
        float fE[4];
#pragma unroll
        for (int qq = 0; qq < 4; qq++) {
            float s = 0.f;
#pragma unroll
            for (int kk = 0; kk < 5; kk++) s = fmaf(fe[kk][qq], fwl[kk], s);
            fE[qq] = fmaxf(s, 0.f);
        }
        float hv[4] = {fmaxf(vv.x, 0.f), fmaxf(vv.y, 0.f),
                       fmaxf(vv.z, 0.f), fmaxf(vv.w, 0.f)};

        float oacc[5];
#pragma unroll
        for (int kk = 0; kk < 5; kk++) {
            float s = hv[0] * wv[kk][0] + hv[1] * wv[kk][1]
                    + hv[2] * wv[kk][2] + hv[3] * wv[kk][3]
                    + fE[0] * wf[kk][0] + fE[1] * wf[kk][1]
                    + fE[2] * wf[kk][2] + fE[3] * wf[kk][3];
#pragma unroll
            for (int o = 16; o > 0; o >>= 1) s += __shfl_xor_sync(0xFFFFFFFFu, s, o);
            oacc[kk] = s;
        }
        if (lane == 0) {
#pragma unroll
            for (int kk = 0; kk < 5; kk++) wred[kk][wid] = oacc[kk];
        }
        __syncthreads();
        if (tid < 5) {
            float s = 0.f;
#pragma unroll
            for (int w = 0; w < 8; w++) s += wred[tid][w];
            out[b * 5 + tid] = s + bout[tid];
        }
        __syncthreads();
    }
}

extern "C" void kernel_launch(void* const* d_in, const int* in_sizes, int n_in,
                              void* d_out, int out_size)
{
    const float* x    = (const float*)d_in[0];   // (4096, 8, 2048)
    const float* stat = (const float*)d_in[1];   // (5, 2048, 512)
    const float* Wk   = (const float*)d_in[2];   // (1024, 2048)
    const float* bk   = (const float*)d_in[3];
    const float* Wv   = (const float*)d_in[4];
    const float* bv   = (const float*)d_in[5];
    const float* WEk  = (const float*)d_in[6];
    const float* bEk  = (const float*)d_in[7];
    const float* WEv  = (const float*)d_in[8];
    const float* bEv  = (const float*)d_in[9];
    const float* Ww   = (const float*)d_in[10];
    const float* bw   = (const float*)d_in[11];
    const float* Wout = (const float*)d_in[12];  // (5, 2048)
    const float* bout = (const float*)d_in[13];
    float* out = (float*)d_out;                  // (4096, 5, 1)

    float *kv_, *sim_, *invE_, *bkv_;
    __half *kn_, *EkT_, *Ev_, *wh_, *feh_, *xl_, *wtf_, *stT_;
    cudaGetSymbolAddress((void**)&kv_,  g_kv);
    cudaGetSymbolAddress((void**)&kn_,  g_kn);
    cudaGetSymbolAddress((void**)&EkT_, g_EkT);
    cudaGetSymbolAddress((void**)&Ev_,  g_Ev);
    cudaGetSymbolAddress((void**)&sim_, g_sim);
    cudaGetSymbolAddress((void**)&wh_,  g_wh);
    cudaGetSymbolAddress((void**)&feh_, g_feh);
    cudaGetSymbolAddress((void**)&invE_, g_invE);
    cudaGetSymbolAddress((void**)&xl_,  g_xl);
    cudaGetSymbolAddress((void**)&wtf_, g_wtf);
    cudaGetSymbolAddress((void**)&stT_, g_stT);
    cudaGetSymbolAddress((void**)&bkv_, g_bkv);

    constexpr int SMEM = 4 * 2 * 128 * 40 * 2;   // 81920 B (4 stages)
    cudaFuncSetAttribute(gemm_h<0>, cudaFuncAttributeMaxDynamicSharedMemorySize, SMEM);
    cudaFuncSetAttribute(gemm_h<1>, cudaFuncAttributeMaxDynamicSharedMemorySize, SMEM);

    // ---- preprocessing (fp16 conversion, transpose, gathers) ----
    gather_x_kernel<<<(4096 * 512) / 256, 256>>>(x, (__half2*)xl_);
    cvt_h_kernel<<<2048, 256>>>((const float4*)Wk,  (__half2*)(wtf_ + 0L * 1024 * 2048), 1024 * 2048 / 4);
    cvt_h_kernel<<<2048, 256>>>((const float4*)Wv,  (__half2*)(wtf_ + 1L * 1024 * 2048), 1024 * 2048 / 4);
    cvt_h_kernel<<<2048, 256>>>((const float4*)WEk, (__half2*)(wtf_ + 2L * 1024 * 2048), 1024 * 2048 / 4);
    cvt_h_kernel<<<2048, 256>>>((const float4*)WEv, (__half2*)(wtf_ + 3L * 1024 * 2048), 1024 * 2048 / 4);
    transpose_static_kernel<<<dim3(64, 16, 5), dim3(32, 8)>>>(stat, stT_);
    concat_bias_kernel<<<8, 256>>>(bk, bv, bkv_);

    // ---- [k|v] = x_last @ [Wk;Wv]^T + [bk;bv]  (NT, 4096x2048x2048, fp32 out) ----
    gemm_h<0><<<dim3(16, 32, 1), 256, SMEM>>>(xl_, 2048, 0,
                                              wtf_, 2048, 0,
                                              kv_, 2048, 0, 2048, nullptr, bkv_);

    // ---- EkT[z][n][c] = staticT[z] @ WEk^T + bEk (NT, 512x1024x2048, fp16 out) ----
    gemm_h<1><<<dim3(8, 4, 5), 256, SMEM>>>(stT_, 2048, (long)512 * 2048,
                                            wtf_ + 2L * 1024 * 2048, 2048, 0,
                                            EkT_, 1024, (long)512 * 1024, 2048, nullptr, bEk);

    // ---- Ev[z][c][n] = WEv @ staticT[z]^T + bEv (NT, 1024x512x2048, fp16 out) ----
    gemm_h<1><<<dim3(4, 8, 5), 256, SMEM>>>(wtf_ + 3L * 1024 * 2048, 2048, 0,
                                            stT_, 2048, (long)512 * 2048,
                                            Ev_, 512, (long)1024 * 512, 2048, bEv, nullptr);

    ssqE_kernel<<<5 * 512, 256>>>(EkT_, invE_);
    norm_rows_kernel<<<4096, 256>>>(kv_, kn_);

    // ---- sim = kn @ EkT^T (NT, 4096x512x1024, z=5), fp32 out, ldc=2560 ----
    gemm_h<0><<<dim3(4, 32, 5), 256, SMEM>>>(kn_, 1024, 0,
                                             EkT_, 1024, (long)512 * 1024,
                                             sim_, 5 * 512, 512, 1024, nullptr, nullptr);

    softmax_kernel<<<4096 * 5, 128>>>(sim_, invE_, wh_);

    // ---- fe = w @ Ev^T (NT, 4096x1024x512, z=5), fp16 out ----
    gemm_h<1><<<dim3(8, 32, 5), 256, SMEM>>>(wh_, 5 * 512, 512,
                                             Ev_, 512, (long)1024 * 512,
                                             feh_, 1024, (long)4096 * 1024, 512, nullptr, nullptr);

    final_kernel<<<256, 256>>>(kv_, feh_, Ww, bw, Wout, bout, out);
}

// round 9
// speedup vs baseline: 5.7801x; 1.0750x over previous
#include <cuda_runtime.h>
#include <cuda_fp16.h>
#include <math.h>

// Problem dims (fixed): B=4096, T=8, CH_IN=2048, C=1024, N=512, K=5, EPS=1e-8

__device__ __half g_kvh[4096u * 2048u];          // [k | v] fp16 (GEMM out)
__device__ __half g_kn [4096u * 1024u];          // normalized k, fp16
__device__ __half g_E2 [5u * 512u * 2048u];      // [EkT | EvT] [z][n][j], fp16 (bias added)
__device__ __half g_Ev [5u * 1024u * 512u];      // Ev  [z][c][n], fp16 (from E2 transpose)
__device__ __half g_simh[4096u * 5u * 512u];     // sim fp16
__device__ __half g_wh [4096u * 5u * 512u];      // softmax weights fp16
__device__ __half g_feh[5u * 4096u * 1024u];     // feature_E fp16, [z][b][c]
__device__ float  g_invE[5u * 512u];             // 1/max(||Ek col||, eps)
__device__ __half g_xl [4096u * 2048u];          // x_last fp16
__device__ __half g_wtf[4u * 1024u * 2048u];     // Wk|Wv|WEk|WEv fp16 (contiguous)
__device__ __half g_stT[5u * 512u * 2048u];      // static transposed [z][n][i] fp16
__device__ float  g_bkv[2048u];                  // bk | bv
__device__ float  g_bE2[2048u];                  // bEk | bEv

#define DINLINE __device__ __forceinline__

DINLINE void mma_f16(float* c, const unsigned* a, const unsigned* b) {
    asm volatile(
        "mma.sync.aligned.m16n8k16.row.col.f32.f16.f16.f32 "
        "{%0,%1,%2,%3}, {%4,%5,%6,%7}, {%8,%9}, {%0,%1,%2,%3};"
        : "+f"(c[0]), "+f"(c[1]), "+f"(c[2]), "+f"(c[3])
        : "r"(a[0]), "r"(a[1]), "r"(a[2]), "r"(a[3]),
          "r"(b[0]), "r"(b[1]));
}

DINLINE void ldsm4(unsigned& r0, unsigned& r1, unsigned& r2, unsigned& r3, unsigned saddr) {
    asm volatile("ldmatrix.sync.aligned.m8n8.x4.shared.b16 {%0,%1,%2,%3}, [%4];"
                 : "=r"(r0), "=r"(r1), "=r"(r2), "=r"(r3) : "r"(saddr));
}

DINLINE void cp16(void* dst_smem, const void* src) {
    unsigned d = (unsigned)__cvta_generic_to_shared(dst_smem);
    asm volatile("cp.async.cg.shared.global [%0], [%1], 16;" :: "r"(d), "l"(src));
}
DINLINE void cp_commit() { asm volatile("cp.async.commit_group;"); }
DINLINE void cp_wait2()  { asm volatile("cp.async.wait_group 2;"); }
DINLINE void cp_wait0()  { asm volatile("cp.async.wait_group 0;"); }

// ---------------------------------------------------------------------------
// FP16 NT GEMM (C = A * B^T), fp32 accumulate. cp.async 4-stage + ldmatrix.
// 128x128x32 block tile, 256 threads (2x4 warps), warp = 64x32 m16n8k16.
// SMEM rows stride 40 halves (80B) -> ldmatrix conflict-free, cp16-aligned.
// C is __half (bias added in fp32, then rounded).
// ---------------------------------------------------------------------------
__global__ __launch_bounds__(256, 2)
void gemm_h(const __half* __restrict__ A, long lda, long sAz,
            const __half* __restrict__ Bm, long ldb, long sBz,
            __half* __restrict__ Cm, long ldc, long sCz,
            int Kd,
            const float* __restrict__ bias_n)
{
    constexpr int ST = 40;                     // halves per smem row
    constexpr unsigned ABYTES = 128 * ST * 2;  // 10240
    constexpr unsigned STAGE  = 2 * ABYTES;    // 20480

    extern __shared__ char smem[];
    const unsigned shb = (unsigned)__cvta_generic_to_shared(smem);

    A  += (long)blockIdx.z * sAz;
    Bm += (long)blockIdx.z * sBz;
    Cm += (long)blockIdx.z * sCz;
    const int m0 = blockIdx.y * 128;
    const int n0 = blockIdx.x * 128;
    const int tid  = threadIdx.x;
    const int lane = tid & 31;
    const int wid  = tid >> 5;
    const int g  = lane >> 2;
    const int tg = lane & 3;
    const int m_w = (wid & 1) * 64;
    const int n_w = (wid >> 1) * 32;

    // ldmatrix address roles (quad q = lane>>3, rr = lane&7)
    const int rr = lane & 7, q = lane >> 3;
    const int arow = ((q & 1) << 3) + rr;
    const int acol = (q >> 1) << 3;            // halves: +0 / +8 (16B)
    const int brow = ((q >> 1) << 3) + rr;
    const int bcol = (q & 1) << 3;

    unsigned aoff[4], boff[2];
#pragma unroll
    for (int mt = 0; mt < 4; mt++)
        aoff[mt] = ((m_w + mt * 16 + arow) * ST + acol) * 2;
#pragma unroll
    for (int nt2 = 0; nt2 < 2; nt2++)
        boff[nt2] = ABYTES + ((n_w + nt2 * 16 + brow) * ST + bcol) * 2;

    float acc[4][4][4];
#pragma unroll
    for (int i = 0; i < 4; i++)
#pragma unroll
        for (int j = 0; j < 4; j++)
#pragma unroll
            for (int p = 0; p < 4; p++) acc[i][j][p] = 0.f;

    auto issue = [&](int t) {
        const int kt = t << 5;                 // halves
        char* stg = smem + (unsigned)(t & 3) * STAGE;
#pragma unroll
        for (int i = 0; i < 2; i++) {          // A: 128 rows x 4 chunks of 16B
            int lin = i * 256 + tid;
            int r = lin >> 2, c = lin & 3;
            cp16(stg + r * 80 + c * 16, A + (long)(m0 + r) * lda + kt + c * 8);
        }
#pragma unroll
        for (int i = 0; i < 2; i++) {          // B: 128 rows x 4 chunks
            int lin = i * 256 + tid;
            int r = lin >> 2, c = lin & 3;
            cp16(stg + ABYTES + r * 80 + c * 16, Bm + (long)(n0 + r) * ldb + kt + c * 8);
        }
        cp_commit();
    };

    const int KT = Kd >> 5;
    issue(0);
    issue(1);
    issue(2);

    for (int t = 0; t < KT; t++) {
        cp_wait2();            // chunk t landed; t+1, t+2 may be in flight
        __syncthreads();
        int tn = t + 3;
        if (tn < KT) issue(tn); else cp_commit();

        const unsigned stb = shb + (unsigned)(t & 3) * STAGE;
#pragma unroll
        for (int s = 0; s < 2; s++) {          // two k16 steps per chunk
            const unsigned kb = s * 32;        // 16 halves = 32B
            unsigned af[4][4], bf[4][2];
#pragma unroll
            for (int mt = 0; mt < 4; mt++)
                ldsm4(af[mt][0], af[mt][1], af[mt][2], af[mt][3], stb + aoff[mt] + kb);
#pragma unroll
            for (int nt2 = 0; nt2 < 2; nt2++)
                ldsm4(bf[2 * nt2][0], bf[2 * nt2][1],
                      bf[2 * nt2 + 1][0], bf[2 * nt2 + 1][1], stb + boff[nt2] + kb);
#pragma unroll
            for (int mt = 0; mt < 4; mt++)
#pragma unroll
                for (int nt = 0; nt < 4; nt++)
                    mma_f16(acc[mt][nt], af[mt], bf[nt]);
        }
    }
    cp_wait0();

    // Epilogue: c0:(g,2tg) c1:(g,2tg+1) c2:(g+8,2tg) c3:(g+8,2tg+1)
#pragma unroll
    for (int mt = 0; mt < 4; mt++) {
        int r0 = m0 + m_w + mt * 16 + g;
#pragma unroll
        for (int nt = 0; nt < 4; nt++) {
            int cc = n0 + n_w + nt * 8 + 2 * tg;
            float bn0 = bias_n ? bias_n[cc]     : 0.f;
            float bn1 = bias_n ? bias_n[cc + 1] : 0.f;
            const float* c = acc[mt][nt];
            *(__half2*)(Cm + (long)r0 * ldc + cc) =
                __floats2half2_rn(c[0] + bn0, c[1] + bn1);
            *(__half2*)(Cm + (long)(r0 + 8) * ldc + cc) =
                __floats2half2_rn(c[2] + bn0, c[3] + bn1);
        }
    }
}

// --- pre-processing ---------------------------------------------------------
// Convert 4 weight matrices (1024x2048 each) to fp16. grid (2048, 4).
__global__ void cvt_w_kernel(const float4* __restrict__ p0, const float4* __restrict__ p1,
                             const float4* __restrict__ p2, const float4* __restrict__ p3,
                             __half2* __restrict__ out)
{
    int i = blockIdx.x * blockDim.x + threadIdx.x;   // float4 idx, 524288 per matrix
    int m = blockIdx.y;
    const float4* src = (m == 0) ? p0 : (m == 1) ? p1 : (m == 2) ? p2 : p3;
    float4 v = src[i];
    __half2* dst = out + (long)m * 524288 * 2;
    dst[2 * i]     = __floats2half2_rn(v.x, v.y);
    dst[2 * i + 1] = __floats2half2_rn(v.z, v.w);
}

__global__ void gather_x_kernel(const float* __restrict__ x, __half2* __restrict__ out)
{
    int i = blockIdx.x * blockDim.x + threadIdx.x;    // float4 index over 4096*512
    int b  = i >> 9;
    int c4 = (i & 511) * 4;
    float4 v = *(const float4*)(x + (long)b * 16384 + 14336 + c4);
    out[(long)b * 1024 + (i & 511) * 2]     = __floats2half2_rn(v.x, v.y);
    out[(long)b * 1024 + (i & 511) * 2 + 1] = __floats2half2_rn(v.z, v.w);
}

// static [z][i=2048][n=512] fp32 -> stT [z][n][i=2048] fp16. 32x32 tiles.
__global__ void transpose_static_kernel(const float* __restrict__ in, __half* __restrict__ out)
{
    __shared__ float tile[32][33];
    int z = blockIdx.z;
    int i0 = blockIdx.x * 32;
    int n0 = blockIdx.y * 32;
    const float* src = in + (long)z * 2048 * 512;
    __half* dst = out + (long)z * 512 * 2048;
#pragma unroll
    for (int d = 0; d < 4; d++) {
        int row = i0 + threadIdx.y + d * 8;
        tile[threadIdx.y + d * 8][threadIdx.x] = src[(long)row * 512 + n0 + threadIdx.x];
    }
    __syncthreads();
#pragma unroll
    for (int d = 0; d < 4; d++) {
        int n = n0 + threadIdx.y + d * 8;
        dst[(long)n * 2048 + i0 + threadIdx.x] =
            __float2half_rn(tile[threadIdx.x][threadIdx.y + d * 8]);
    }
}

// EvT part of E2 ([z][n][1024+c]) -> Ev [z][c][n]. 32x32 fp16 tiles.
__global__ void transpose_Ev_kernel(const __half* __restrict__ E2, __half* __restrict__ Ev)
{
    __shared__ __half tile[32][33];
    int z = blockIdx.z;
    int c0 = blockIdx.x * 32;
    int n0 = blockIdx.y * 32;
    const __half* src = E2 + (long)z * 512 * 2048 + 1024;
    __half* dst = Ev + (long)z * 1024 * 512;
#pragma unroll
    for (int d = 0; d < 4; d++) {
        int n = n0 + threadIdx.y + d * 8;
        tile[threadIdx.y + d * 8][threadIdx.x] = src[(long)n * 2048 + c0 + threadIdx.x];
    }
    __syncthreads();
#pragma unroll
    for (int d = 0; d < 4; d++) {
        int c = c0 + threadIdx.y + d * 8;
        dst[(long)c * 512 + n0 + threadIdx.x] = tile[threadIdx.x][threadIdx.y + d * 8];
    }
}

__global__ void concat_bias_kernel(const float* __restrict__ b0, const float* __restrict__ b1,
                                   float* __restrict__ o)
{
    int i = blockIdx.x * blockDim.x + threadIdx.x;
    if (i < 2048) o[i] = (i < 1024) ? b0[i] : b1[i - 1024];
}

// inv col norms from Ek rows of E2 (row stride 2048, first 1024 halves).
__global__ void ssqE_kernel(const __half* __restrict__ E2, float* __restrict__ invE)
{
    int row = blockIdx.x;                      // z*512 + n
    const __half2* base = (const __half2*)(E2 + (long)row * 2048);
    int tid = threadIdx.x;
    float2 a = __half22float2(base[tid * 2]);
    float2 b = __half22float2(base[tid * 2 + 1]);
    __shared__ float red[256];
    red[tid] = a.x * a.x + a.y * a.y + b.x * b.x + b.y * b.y;
    __syncthreads();
    for (int st = 128; st > 0; st >>= 1) {
        if (tid < st) red[tid] += red[tid + st];
        __syncthreads();
    }
    if (tid == 0) invE[row] = 1.f / fmaxf(sqrtf(red[0]), 1e-8f);
}

// normalize k (first 1024 cols of fp16 kv row), write fp16 kn. grid=B, 256 thr.
__global__ void norm_rows_kernel(const __half* __restrict__ KV, __half* __restrict__ KN)
{
    int b = blockIdx.x, tid = threadIdx.x;
    const __half2* row = (const __half2*)(KV + (long)b * 2048);
    float2 a = __half22float2(row[tid * 2]);
    float2 c = __half22float2(row[tid * 2 + 1]);
    __shared__ float sred[256];
    sred[tid] = a.x * a.x + a.y * a.y + c.x * c.x + c.y * c.y;
    __syncthreads();
    for (int st = 128; st > 0; st >>= 1) {
        if (tid < st) sred[tid] += sred[tid + st];
        __syncthreads();
    }
    float inv = 1.f / fmaxf(sqrtf(sred[0]), 1e-8f);
    __half2* o = (__half2*)(KN + (long)b * 1024);
    o[tid * 2]     = __floats2half2_rn(a.x * inv, a.y * inv);
    o[tid * 2 + 1] = __floats2half2_rn(c.x * inv, c.y * inv);
}

// scale by invE, softmax over 512, fp16 in / fp16 out. row = b*5+z.
__global__ void softmax_kernel(const __half* __restrict__ S, const float* __restrict__ invE,
                               __half* __restrict__ W)
{
    int row = blockIdx.x;
    int z = row % 5;
    const __half2* base = (const __half2*)(S + (long)row * 512);
    int tid = threadIdx.x;
    float2 a = __half22float2(base[tid * 2]);
    float2 b = __half22float2(base[tid * 2 + 1]);
    float4 v = make_float4(a.x, a.y, b.x, b.y);
    float4 e = *(const float4*)&invE[z * 512 + tid * 4];
    v.x *= e.x; v.y *= e.y; v.z *= e.z; v.w *= e.w;
    __shared__ float sred[128];
    sred[tid] = fmaxf(fmaxf(v.x, v.y), fmaxf(v.z, v.w));
    __syncthreads();
    for (int st = 64; st > 0; st >>= 1) {
        if (tid < st) sred[tid] = fmaxf(sred[tid], sred[tid + st]);
        __syncthreads();
    }
    float m = sred[0];
    __syncthreads();
    v.x = expf(v.x - m); v.y = expf(v.y - m); v.z = expf(v.z - m); v.w = expf(v.w - m);
    sred[tid] = v.x + v.y + v.z + v.w;
    __syncthreads();
    for (int st = 64; st > 0; st >>= 1) {
        if (tid < st) sred[tid] += sred[tid + st];
        __syncthreads();
    }
    float inv = 1.f / sred[0];
    __half2* o = (__half2*)(W + (long)row * 512);
    o[tid * 2]     = __floats2half2_rn(v.x * inv, v.y * inv);
    o[tid * 2 + 1] = __floats2half2_rn(v.z * inv, v.w * inv);
}

// ---------------------------------------------------------------------------
// Final stage: gate + concat + output GEMV. grid = B/16, 256 threads.
// ---------------------------------------------------------------------------
__global__ __launch_bounds__(256)
void final_kernel(const __half* __restrict__ kvh,
                  const __half* __restrict__ feh,
                  const float* __restrict__ Ww,
                  const float* __restrict__ bw,
                  const float* __restrict__ Wout,
                  const float* __restrict__ bout,
                  float* __restrict__ out)
{
    const int tid = threadIdx.x, lane = tid & 31, wid = tid >> 5;
    const int c0 = tid * 4;
    const long sz = (long)4096 * 1024;

    float ww[4];
    float wv[5][4], wf[5][4];
    *(float4*)ww = *(const float4*)&Ww[c0];
#pragma unroll
    for (int kk = 0; kk < 5; kk++) {
        *(float4*)wv[kk] = *(const float4*)&Wout[kk * 2048 + c0];
        *(float4*)wf[kk] = *(const float4*)&Wout[kk * 2048 + 1024 + c0];
    }
    const float bwv = bw[0];

    __shared__ float wred[5][8];
    __shared__ float s_fw[5];

    for (int bi = 0; bi < 16; bi++) {
        const int b = blockIdx.x * 16 + bi;
        const long bc = (long)b * 1024 + c0;

        float fe[5][4];
#pragma unroll
        for (int kk = 0; kk < 5; kk++) {
            __half2 h0 = *(const __half2*)(feh + sz * kk + bc);
            __half2 h1 = *(const __half2*)(feh + sz * kk + bc + 2);
            float2 f0 = __half22float2(h0), f1 = __half22float2(h1);
            fe[kk][0] = f0.x; fe[kk][1] = f0.y; fe[kk][2] = f1.x; fe[kk][3] = f1.y;
        }
        __half2 v0 = *(const __half2*)(kvh + (long)b * 2048 + 1024 + c0);
        __half2 v1 = *(const __half2*)(kvh + (long)b * 2048 + 1024 + c0 + 2);
        float2 vf0 = __half22float2(v0), vf1 = __half22float2(v1);

        float acc[5];
#pragma unroll
        for (int kk = 0; kk < 5; kk++) {
            float s = fe[kk][0] * ww[0] + fe[kk][1] * ww[1]
                    + fe[kk][2] * ww[2] + fe[kk][3] * ww[3];
#pragma unroll
            for (int o = 16; o > 0; o >>= 1) s += __shfl_xor_sync(0xFFFFFFFFu, s, o);
            acc[kk] = s;
        }
        if (lane == 0) {
#pragma unroll
            for (int kk = 0; kk < 5; kk++) wred[kk][wid] = acc[kk];
        }
        __syncthreads();
        if (tid < 5) {
            float s = 0.f;
#pragma unroll
            for (int w = 0; w < 8; w++) s += wred[tid][w];
            s_fw[tid] = 1.f / (1.f + expf(-(s + bwv)));
        }
        __syncthreads();
        float fwl[5];
#pragma unroll
        for (int kk = 0; kk < 5; kk++) fwl[kk] = s_fw[kk];

        float fE[4];
#pragma unroll
        for (int qq = 0; qq < 4; qq++) {
            float s = 0.f;
#pragma unroll
            for (int kk = 0; kk < 5; kk++) s = fmaf(fe[kk][qq], fwl[kk], s);
            fE[qq] = fmaxf(s, 0.f);
        }
        float hv[4] = {fmaxf(vf0.x, 0.f), fmaxf(vf0.y, 0.f),
                       fmaxf(vf1.x, 0.f), fmaxf(vf1.y, 0.f)};

        float oacc[5];
#pragma unroll
        for (int kk = 0; kk < 5; kk++) {
            float s = hv[0] * wv[kk][0] + hv[1] * wv[kk][1]
                    + hv[2] * wv[kk][2] + hv[3] * wv[kk][3]
                    + fE[0] * wf[kk][0] + fE[1] * wf[kk][1]
                    + fE[2] * wf[kk][2] + fE[3] * wf[kk][3];
#pragma unroll
            for (int o = 16; o > 0; o >>= 1) s += __shfl_xor_sync(0xFFFFFFFFu, s, o);
            oacc[kk] = s;
        }
        if (lane == 0) {
#pragma unroll
            for (int kk = 0; kk < 5; kk++) wred[kk][wid] = oacc[kk];
        }
        __syncthreads();
        if (tid < 5) {
            float s = 0.f;
#pragma unroll
            for (int w = 0; w < 8; w++) s += wred[tid][w];
            out[b * 5 + tid] = s + bout[tid];
        }
        __syncthreads();
    }
}

extern "C" void kernel_launch(void* const* d_in, const int* in_sizes, int n_in,
                              void* d_out, int out_size)
{
    const float* x    = (const float*)d_in[0];   // (4096, 8, 2048)
    const float* stat = (const float*)d_in[1];   // (5, 2048, 512)
    const float* Wk   = (const float*)d_in[2];   // (1024, 2048)
    const float* bk   = (const float*)d_in[3];
    const float* Wv   = (const float*)d_in[4];
    const float* bv   = (const float*)d_in[5];
    const float* WEk  = (const float*)d_in[6];
    const float* bEk  = (const float*)d_in[7];
    const float* WEv  = (const float*)d_in[8];
    const float* bEv  = (const float*)d_in[9];
    const float* Ww   = (const float*)d_in[10];
    const float* bw   = (const float*)d_in[11];
    const float* Wout = (const float*)d_in[12];  // (5, 2048)
    const float* bout = (const float*)d_in[13];
    float* out = (float*)d_out;                  // (4096, 5, 1)

    float *invE_, *bkv_, *bE2_;
    __half *kvh_, *kn_, *E2_, *Ev_, *simh_, *wh_, *feh_, *xl_, *wtf_, *stT_;
    cudaGetSymbolAddress((void**)&kvh_, g_kvh);
    cudaGetSymbolAddress((void**)&kn_,  g_kn);
    cudaGetSymbolAddress((void**)&E2_,  g_E2);
    cudaGetSymbolAddress((void**)&Ev_,  g_Ev);
    cudaGetSymbolAddress((void**)&simh_, g_simh);
    cudaGetSymbolAddress((void**)&wh_,  g_wh);
    cudaGetSymbolAddress((void**)&feh_, g_feh);
    cudaGetSymbolAddress((void**)&invE_, g_invE);
    cudaGetSymbolAddress((void**)&xl_,  g_xl);
    cudaGetSymbolAddress((void**)&wtf_, g_wtf);
    cudaGetSymbolAddress((void**)&stT_, g_stT);
    cudaGetSymbolAddress((void**)&bkv_, g_bkv);
    cudaGetSymbolAddress((void**)&bE2_, g_bE2);

    constexpr int SMEM = 4 * 2 * 128 * 40 * 2;   // 81920 B (4 stages)
    cudaFuncSetAttribute(gemm_h, cudaFuncAttributeMaxDynamicSharedMemorySize, SMEM);

    // ---- preprocessing ----
    gather_x_kernel<<<(4096 * 512) / 256, 256>>>(x, (__half2*)xl_);
    cvt_w_kernel<<<dim3(2048, 4), 256>>>((const float4*)Wk, (const float4*)Wv,
                                         (const float4*)WEk, (const float4*)WEv,
                                         (__half2*)wtf_);
    transpose_static_kernel<<<dim3(64, 16, 5), dim3(32, 8)>>>(stat, stT_);
    concat_bias_kernel<<<8, 256>>>(bk, bv, bkv_);
    concat_bias_kernel<<<8, 256>>>(bEk, bEv, bE2_);

    // ---- [k|v] = x_last @ [Wk;Wv]^T + [bk;bv]  (NT, 4096x2048x2048, fp16 out) ----
    gemm_h<<<dim3(16, 32, 1), 256, SMEM>>>(xl_, 2048, 0,
                                           wtf_, 2048, 0,
                                           kvh_, 2048, 0, 2048, bkv_);

    // ---- E2[z][n][j] = staticT[z] @ [WEk;WEv]^T + [bEk|bEv]  (NT, 512x2048x2048) ----
    gemm_h<<<dim3(16, 4, 5), 256, SMEM>>>(stT_, 2048, (long)512 * 2048,
                                          wtf_ + 2L * 1024 * 2048, 2048, 0,
                                          E2_, 2048, (long)512 * 2048, 2048, bE2_);

    transpose_Ev_kernel<<<dim3(32, 16, 5), dim3(32, 8)>>>(E2_, Ev_);
    ssqE_kernel<<<5 * 512, 256>>>(E2_, invE_);
    norm_rows_kernel<<<4096, 256>>>(kvh_, kn_);

    // ---- sim = kn @ EkT^T (NT, 4096x512x1024, z=5), fp16 out, ldc=2560 ----
    gemm_h<<<dim3(4, 32, 5), 256, SMEM>>>(kn_, 1024, 0,
                                          E2_, 2048, (long)512 * 2048,
                                          simh_, 5 * 512, 512, 1024, nullptr);

    softmax_kernel<<<4096 * 5, 128>>>(simh_, invE_, wh_);

    // ---- fe = w @ Ev^T (NT, 4096x1024x512, z=5), fp16 out ----
    gemm_h<<<dim3(8, 32, 5), 256, SMEM>>>(wh_, 5 * 512, 512,
                                          Ev_, 512, (long)1024 * 512,
                                          feh_, 1024, (long)4096 * 1024, 512, nullptr);

    final_kernel<<<256, 256>>>(kvh_, feh_, Ww, bw, Wout, bout, out);
}

// round 10
// speedup vs baseline: 6.5278x; 1.1294x over previous
#include <cuda_runtime.h>
#include <cuda_fp16.h>
#include <math.h>

// Problem dims (fixed): B=4096, T=8, CH_IN=2048, C=1024, N=512, K=5, EPS=1e-8

__device__ __half g_kvh[4096u * 2048u];          // [k | v] fp16 (GEMM out)
__device__ __half g_kn [4096u * 1024u];          // normalized k, fp16
__device__ __half g_E2 [5u * 512u * 2048u];      // [EkT | EvT] [z][n][j], fp16 (bias added)
__device__ __half g_Ev [5u * 1024u * 512u];      // Ev  [z][c][n], fp16 (from E2 transpose)
__device__ __half g_simh[4096u * 5u * 512u];     // sim fp16
__device__ __half g_wh [4096u * 5u * 512u];      // softmax weights fp16
__device__ __half g_feh[5u * 4096u * 1024u];     // feature_E fp16, [z][b][c]
__device__ float  g_invE[5u * 512u];             // 1/max(||Ek col||, eps)
__device__ __half g_xl [4096u * 2048u];          // x_last fp16
__device__ __half g_wtf[4u * 1024u * 2048u];     // Wk|Wv|WEk|WEv fp16 (contiguous)
__device__ __half g_stT[5u * 512u * 2048u];      // static transposed [z][n][i] fp16
__device__ float  g_bkv[2048u];                  // bk | bv
__device__ float  g_bE2[2048u];                  // bEk | bEv

#define DINLINE __device__ __forceinline__

DINLINE void mma_f16(float* c, const unsigned* a, const unsigned* b) {
    asm volatile(
        "mma.sync.aligned.m16n8k16.row.col.f32.f16.f16.f32 "
        "{%0,%1,%2,%3}, {%4,%5,%6,%7}, {%8,%9}, {%0,%1,%2,%3};"
        : "+f"(c[0]), "+f"(c[1]), "+f"(c[2]), "+f"(c[3])
        : "r"(a[0]), "r"(a[1]), "r"(a[2]), "r"(a[3]),
          "r"(b[0]), "r"(b[1]));
}

DINLINE void ldsm4(unsigned& r0, unsigned& r1, unsigned& r2, unsigned& r3, unsigned saddr) {
    asm volatile("ldmatrix.sync.aligned.m8n8.x4.shared.b16 {%0,%1,%2,%3}, [%4];"
                 : "=r"(r0), "=r"(r1), "=r"(r2), "=r"(r3) : "r"(saddr));
}

DINLINE void cp16(void* dst_smem, const void* src) {
    unsigned d = (unsigned)__cvta_generic_to_shared(dst_smem);
    asm volatile("cp.async.cg.shared.global [%0], [%1], 16;" :: "r"(d), "l"(src));
}
DINLINE void cp_commit() { asm volatile("cp.async.commit_group;"); }
DINLINE void cp_wait2()  { asm volatile("cp.async.wait_group 2;"); }
DINLINE void cp_wait0()  { asm volatile("cp.async.wait_group 0;"); }

// ---------------------------------------------------------------------------
// FP16 NT GEMM body (C = A * B^T), fp32 accumulate. cp.async 4-stage + ldmatrix.
// 128x128x32 block tile, 256 threads (2x4 warps), warp = 64x32 m16n8k16.
// SMEM rows stride 40 halves (80B) -> ldmatrix conflict-free, cp16-aligned.
// C is __half (bias added in fp32, then rounded).
// ---------------------------------------------------------------------------
DINLINE void gemm_body(const __half* __restrict__ A, long lda,
                       const __half* __restrict__ Bm, long ldb,
                       __half* __restrict__ Cm, long ldc,
                       int Kd, const float* __restrict__ bias_n,
                       int m0, int n0, char* smem)
{
    constexpr int ST = 40;
    constexpr unsigned ABYTES = 128 * ST * 2;  // 10240
    constexpr unsigned STAGE  = 2 * ABYTES;    // 20480

    const unsigned shb = (unsigned)__cvta_generic_to_shared(smem);
    const int tid  = threadIdx.x;
    const int lane = tid & 31;
    const int wid  = tid >> 5;
    const int g  = lane >> 2;
    const int tg = lane & 3;
    const int m_w = (wid & 1) * 64;
    const int n_w = (wid >> 1) * 32;

    const int rr = lane & 7, q = lane >> 3;
    const int arow = ((q & 1) << 3) + rr;
    const int acol = (q >> 1) << 3;
    const int brow = ((q >> 1) << 3) + rr;
    const int bcol = (q & 1) << 3;

    unsigned aoff[4], boff[2];
#pragma unroll
    for (int mt = 0; mt < 4; mt++)
        aoff[mt] = ((m_w + mt * 16 + arow) * ST + acol) * 2;
#pragma unroll
    for (int nt2 = 0; nt2 < 2; nt2++)
        boff[nt2] = ABYTES + ((n_w + nt2 * 16 + brow) * ST + bcol) * 2;

    float acc[4][4][4];
#pragma unroll
    for (int i = 0; i < 4; i++)
#pragma unroll
        for (int j = 0; j < 4; j++)
#pragma unroll
            for (int p = 0; p < 4; p++) acc[i][j][p] = 0.f;

    auto issue = [&](int t) {
        const int kt = t << 5;
        char* stg = smem + (unsigned)(t & 3) * STAGE;
#pragma unroll
        for (int i = 0; i < 2; i++) {
            int lin = i * 256 + tid;
            int r = lin >> 2, c = lin & 3;
            cp16(stg + r * 80 + c * 16, A + (long)(m0 + r) * lda + kt + c * 8);
        }
#pragma unroll
        for (int i = 0; i < 2; i++) {
            int lin = i * 256 + tid;
            int r = lin >> 2, c = lin & 3;
            cp16(stg + ABYTES + r * 80 + c * 16, Bm + (long)(n0 + r) * ldb + kt + c * 8);
        }
        cp_commit();
    };

    const int KT = Kd >> 5;
    issue(0);
    issue(1);
    issue(2);

    for (int t = 0; t < KT; t++) {
        cp_wait2();
        __syncthreads();
        int tn = t + 3;
        if (tn < KT) issue(tn); else cp_commit();

        const unsigned stb = shb + (unsigned)(t & 3) * STAGE;
#pragma unroll
        for (int s = 0; s < 2; s++) {
            const unsigned kb = s * 32;
            unsigned af[4][4], bf[4][2];
#pragma unroll
            for (int mt = 0; mt < 4; mt++)
                ldsm4(af[mt][0], af[mt][1], af[mt][2], af[mt][3], stb + aoff[mt] + kb);
#pragma unroll
            for (int nt2 = 0; nt2 < 2; nt2++)
                ldsm4(bf[2 * nt2][0], bf[2 * nt2][1],
                      bf[2 * nt2 + 1][0], bf[2 * nt2 + 1][1], stb + boff[nt2] + kb);
#pragma unroll
            for (int mt = 0; mt < 4; mt++)
#pragma unroll
                for (int nt = 0; nt < 4; nt++)
                    mma_f16(acc[mt][nt], af[mt], bf[nt]);
        }
    }
    cp_wait0();

#pragma unroll
    for (int mt = 0; mt < 4; mt++) {
        int r0 = m0 + m_w + mt * 16 + g;
#pragma unroll
        for (int nt = 0; nt < 4; nt++) {
            int cc = n0 + n_w + nt * 8 + 2 * tg;
            float bn0 = bias_n ? bias_n[cc]     : 0.f;
            float bn1 = bias_n ? bias_n[cc + 1] : 0.f;
            const float* c = acc[mt][nt];
            *(__half2*)(Cm + (long)r0 * ldc + cc) =
                __floats2half2_rn(c[0] + bn0, c[1] + bn1);
            *(__half2*)(Cm + (long)(r0 + 8) * ldc + cc) =
                __floats2half2_rn(c[2] + bn0, c[3] + bn1);
        }
    }
}

// Generic batched NT GEMM (used for sim & fe).
__global__ __launch_bounds__(256, 2)
void gemm_h(const __half* __restrict__ A, long lda, long sAz,
            const __half* __restrict__ Bm, long ldb, long sBz,
            __half* __restrict__ Cm, long ldc, long sCz,
            int Kd, const float* __restrict__ bias_n)
{
    extern __shared__ char smem[];
    gemm_body(A + (long)blockIdx.z * sAz, lda,
              Bm + (long)blockIdx.z * sBz, ldb,
              Cm + (long)blockIdx.z * sCz, ldc,
              Kd, bias_n, blockIdx.y * 128, blockIdx.x * 128, smem);
}

// Fused launch: kv GEMM (y<32) + E2 GEMM (y>=32, z=(y-32)/4). K=2048 both,
// ldb=ldc=2048 both. Fills waves: 832 CTAs vs 512+320 with two idle tails.
__global__ __launch_bounds__(256, 2)
void gemm_dual(const __half* __restrict__ xl, const __half* __restrict__ wkv,
               __half* __restrict__ kvh, const float* __restrict__ bkv,
               const __half* __restrict__ stT, const __half* __restrict__ wE,
               __half* __restrict__ E2, const float* __restrict__ bE2)
{
    extern __shared__ char smem[];
    const int y = blockIdx.y;
    if (y < 32) {
        gemm_body(xl, 2048, wkv, 2048, kvh, 2048,
                  2048, bkv, y * 128, blockIdx.x * 128, smem);
    } else {
        int idx = y - 32;
        int z = idx >> 2, my = idx & 3;
        gemm_body(stT + (long)z * 512 * 2048, 2048, wE, 2048,
                  E2 + (long)z * 512 * 2048, 2048,
                  2048, bE2, my * 128, blockIdx.x * 128, smem);
    }
}

// ---------------------------------------------------------------------------
// Fused preprocessing: gather_x | cvt_w | biases | transpose_static.
// 256 threads, 1D grid decode.
//   [0, 8192)          gather x[:,7,:] -> fp16 xl
//   [8192, 16384)      Wk|Wv|WEk|WEv fp32 -> fp16 wtf
//   [16384, 16400)     bkv / bE2 concat (4096 floats)
//   [16400, 21520)     static [z][i][n] -> stT [z][n][i] fp16 (32x32 tiles)
// ---------------------------------------------------------------------------
__global__ __launch_bounds__(256)
void prep_kernel(const float* __restrict__ x,
                 const float* __restrict__ Wk, const float* __restrict__ Wv,
                 const float* __restrict__ WEk, const float* __restrict__ WEv,
                 const float* __restrict__ bk, const float* __restrict__ bv,
                 const float* __restrict__ bEk, const float* __restrict__ bEv,
                 const float* __restrict__ stat,
                 __half2* __restrict__ xl, __half2* __restrict__ wtf,
                 float* __restrict__ bkv, float* __restrict__ bE2,
                 __half* __restrict__ stT)
{
    __shared__ float tile[32][33];
    const int blk = blockIdx.x, tid = threadIdx.x;

    if (blk < 8192) {                                   // gather_x
        int i = blk * 256 + tid;
        int b  = i >> 9;
        int c4 = (i & 511) * 4;
        float4 v = *(const float4*)(x + (long)b * 16384 + 14336 + c4);
        xl[(long)b * 1024 + (i & 511) * 2]     = __floats2half2_rn(v.x, v.y);
        xl[(long)b * 1024 + (i & 511) * 2 + 1] = __floats2half2_rn(v.z, v.w);
    } else if (blk < 16384) {                           // cvt_w
        int j = (blk - 8192) * 256 + tid;
        int m = j >> 19;
        int i = j & 0x7FFFF;
        const float* src = (m == 0) ? Wk : (m == 1) ? Wv : (m == 2) ? WEk : WEv;
        float4 v = ((const float4*)src)[i];
        __half2* dst = wtf + (long)m * 1048576 + 2 * i;
        dst[0] = __floats2half2_rn(v.x, v.y);
        dst[1] = __floats2half2_rn(v.z, v.w);
    } else if (blk < 16400) {                           // biases
        int i = (blk - 16384) * 256 + tid;              // 0..4095
        if (i < 2048) bkv[i] = (i < 1024) ? bk[i] : bv[i - 1024];
        else {
            int j = i - 2048;
            bE2[j] = (j < 1024) ? bEk[j] : bEv[j - 1024];
        }
    } else {                                            // transpose_static
        int t = blk - 16400;                            // 0..5119
        int z = t >> 10;
        int rem = t & 1023;
        int i0 = (rem & 63) * 32;
        int n0 = (rem >> 6) * 32;
        int tx = tid & 31, ty = tid >> 5;
        const float* src = stat + (long)z * 2048 * 512;
        __half* dst = stT + (long)z * 512 * 2048;
#pragma unroll
        for (int d = 0; d < 4; d++) {
            int row = i0 + ty + d * 8;
            tile[ty + d * 8][tx] = src[(long)row * 512 + n0 + tx];
        }
        __syncthreads();
#pragma unroll
        for (int d = 0; d < 4; d++) {
            int n = n0 + ty + d * 8;
            dst[(long)n * 2048 + i0 + tx] = __float2half_rn(tile[tx][ty + d * 8]);
        }
    }
}

// ---------------------------------------------------------------------------
// Fused post-GEMM1: transpose_Ev | ssqE | norm_rows. 256 threads, 1D decode.
//   [0, 2560)      EvT part of E2 -> Ev [z][c][n] (32x32 fp16 tiles)
//   [2560, 5120)   inv col norms of Ek rows (row = blk-2560)
//   [5120, 9216)   normalize k rows -> kn fp16 (b = blk-5120)
// ---------------------------------------------------------------------------
__global__ __launch_bounds__(256)
void post1_kernel(const __half* __restrict__ E2, __half* __restrict__ Ev,
                  float* __restrict__ invE,
                  const __half* __restrict__ KV, __half* __restrict__ KN)
{
    __shared__ float red[256];
    __shared__ __half htile[32][33];
    const int blk = blockIdx.x, tid = threadIdx.x;

    if (blk < 2560) {                                   // transpose_Ev
        int z = blk >> 9;
        int rem = blk & 511;
        int c0 = (rem >> 4) * 32;
        int n0 = (rem & 15) * 32;
        int tx = tid & 31, ty = tid >> 5;
        const __half* src = E2 + (long)z * 512 * 2048 + 1024;
        __half* dst = Ev + (long)z * 1024 * 512;
#pragma unroll
        for (int d = 0; d < 4; d++) {
            int n = n0 + ty + d * 8;
            htile[ty + d * 8][tx] = src[(long)n * 2048 + c0 + tx];
        }
        __syncthreads();
#pragma unroll
        for (int d = 0; d < 4; d++) {
            int c = c0 + ty + d * 8;
            dst[(long)c * 512 + n0 + tx] = htile[tx][ty + d * 8];
        }
    } else if (blk < 5120) {                            // ssqE
        int row = blk - 2560;
        const __half2* base = (const __half2*)(E2 + (long)row * 2048);
        float2 a = __half22float2(base[tid * 2]);
        float2 b = __half22float2(base[tid * 2 + 1]);
        red[tid] = a.x * a.x + a.y * a.y + b.x * b.x + b.y * b.y;
        __syncthreads();
        for (int st = 128; st > 0; st >>= 1) {
            if (tid < st) red[tid] += red[tid + st];
            __syncthreads();
        }
        if (tid == 0) invE[row] = 1.f / fmaxf(sqrtf(red[0]), 1e-8f);
    } else {                                            // norm_rows
        int b = blk - 5120;
        const __half2* row = (const __half2*)(KV + (long)b * 2048);
        float2 a = __half22float2(row[tid * 2]);
        float2 c = __half22float2(row[tid * 2 + 1]);
        red[tid] = a.x * a.x + a.y * a.y + c.x * c.x + c.y * c.y;
        __syncthreads();
        for (int st = 128; st > 0; st >>= 1) {
            if (tid < st) red[tid] += red[tid + st];
            __syncthreads();
        }
        float inv = 1.f / fmaxf(sqrtf(red[0]), 1e-8f);
        __half2* o = (__half2*)(KN + (long)b * 1024);
        o[tid * 2]     = __floats2half2_rn(a.x * inv, a.y * inv);
        o[tid * 2 + 1] = __floats2half2_rn(c.x * inv, c.y * inv);
    }
}

// scale by invE, softmax over 512, fp16 in / fp16 out. row = b*5+z.
__global__ void softmax_kernel(const __half* __restrict__ S, const float* __restrict__ invE,
                               __half* __restrict__ W)
{
    int row = blockIdx.x;
    int z = row % 5;
    const __half2* base = (const __half2*)(S + (long)row * 512);
    int tid = threadIdx.x;
    float2 a = __half22float2(base[tid * 2]);
    float2 b = __half22float2(base[tid * 2 + 1]);
    float4 v = make_float4(a.x, a.y, b.x, b.y);
    float4 e = *(const float4*)&invE[z * 512 + tid * 4];
    v.x *= e.x; v.y *= e.y; v.z *= e.z; v.w *= e.w;
    __shared__ float sred[128];
    sred[tid] = fmaxf(fmaxf(v.x, v.y), fmaxf(v.z, v.w));
    __syncthreads();
    for (int st = 64; st > 0; st >>= 1) {
        if (tid < st) sred[tid] = fmaxf(sred[tid], sred[tid + st]);
        __syncthreads();
    }
    float m = sred[0];
    __syncthreads();
    v.x = expf(v.x - m); v.y = expf(v.y - m); v.z = expf(v.z - m); v.w = expf(v.w - m);
    sred[tid] = v.x + v.y + v.z + v.w;
    __syncthreads();
    for (int st = 64; st > 0; st >>= 1) {
        if (tid < st) sred[tid] += sred[tid + st];
        __syncthreads();
    }
    float inv = 1.f / sred[0];
    __half2* o = (__half2*)(W + (long)row * 512);
    o[tid * 2]     = __floats2half2_rn(v.x * inv, v.y * inv);
    o[tid * 2 + 1] = __floats2half2_rn(v.z * inv, v.w * inv);
}

// ---------------------------------------------------------------------------
// Final stage: gate + concat + output GEMV. grid = B/16, 256 threads.
// ---------------------------------------------------------------------------
__global__ __launch_bounds__(256)
void final_kernel(const __half* __restrict__ kvh,
                  const __half* __restrict__ feh,
                  const float* __restrict__ Ww,
                  const float* __restrict__ bw,
                  const float* __restrict__ Wout,
                  const float* __restrict__ bout,
                  float* __restrict__ out)
{
    const int tid = threadIdx.x, lane = tid & 31, wid = tid >> 5;
    const int c0 = tid * 4;
    const long sz = (long)4096 * 1024;

    float ww[4];
    float wv[5][4], wf[5][4];
    *(float4*)ww = *(const float4*)&Ww[c0];
#pragma unroll
    for (int kk = 0; kk < 5; kk++) {
        *(float4*)wv[kk] = *(const float4*)&Wout[kk * 2048 + c0];
        *(float4*)wf[kk] = *(const float4*)&Wout[kk * 2048 + 1024 + c0];
    }
    const float bwv = bw[0];

    __shared__ float wred[5][8];
    __shared__ float s_fw[5];

    for (int bi = 0; bi < 16; bi++) {
        const int b = blockIdx.x * 16 + bi;
        const long bc = (long)b * 1024 + c0;

        float fe[5][4];
#pragma unroll
        for (int kk = 0; kk < 5; kk++) {
            __half2 h0 = *(const __half2*)(feh + sz * kk + bc);
            __half2 h1 = *(const __half2*)(feh + sz * kk + bc + 2);
            float2 f0 = __half22float2(h0), f1 = __half22float2(h1);
            fe[kk][0] = f0.x; fe[kk][1] = f0.y; fe[kk][2] = f1.x; fe[kk][3] = f1.y;
        }
        __half2 v0 = *(const __half2*)(kvh + (long)b * 2048 + 1024 + c0);
        __half2 v1 = *(const __half2*)(kvh + (long)b * 2048 + 1024 + c0 + 2);
        float2 vf0 = __half22float2(v0), vf1 = __half22float2(v1);

        float acc[5];
#pragma unroll
        for (int kk = 0; kk < 5; kk++) {
            float s = fe[kk][0] * ww[0] + fe[kk][1] * ww[1]
                    + fe[kk][2] * ww[2] + fe[kk][3] * ww[3];
#pragma unroll
            for (int o = 16; o > 0; o >>= 1) s += __shfl_xor_sync(0xFFFFFFFFu, s, o);
            acc[kk] = s;
        }
        if (lane == 0) {
#pragma unroll
            for (int kk = 0; kk < 5; kk++) wred[kk][wid] = acc[kk];
        }
        __syncthreads();
        if (tid < 5) {
            float s = 0.f;
#pragma unroll
            for (int w = 0; w < 8; w++) s += wred[tid][w];
            s_fw[tid] = 1.f / (1.f + expf(-(s + bwv)));
        }
        __syncthreads();
        float fwl[5];
#pragma unroll
        for (int kk = 0; kk < 5; kk++) fwl[kk] = s_fw[kk];

        float fE[4];
#pragma unroll
        for (int qq = 0; qq < 4; qq++) {
            float s = 0.f;
#pragma unroll
            for (int kk = 0; kk < 5; kk++) s = fmaf(fe[kk][qq], fwl[kk], s);
            fE[qq] = fmaxf(s, 0.f);
        }
        float hv[4] = {fmaxf(vf0.x, 0.f), fmaxf(vf0.y, 0.f),
                       fmaxf(vf1.x, 0.f), fmaxf(vf1.y, 0.f)};

        float oacc[5];
#pragma unroll
        for (int kk = 0; kk < 5; kk++) {
            float s = hv[0] * wv[kk][0] + hv[1] * wv[kk][1]
                    + hv[2] * wv[kk][2] + hv[3] * wv[kk][3]
                    + fE[0] * wf[kk][0] + fE[1] * wf[kk][1]
                    + fE[2] * wf[kk][2] + fE[3] * wf[kk][3];
#pragma unroll
            for (int o = 16; o > 0; o >>= 1) s += __shfl_xor_sync(0xFFFFFFFFu, s, o);
            oacc[kk] = s;
        }
        if (lane == 0) {
#pragma unroll
            for (int kk = 0; kk < 5; kk++) wred[kk][wid] = oacc[kk];
        }
        __syncthreads();
        if (tid < 5) {
            float s = 0.f;
#pragma unroll
            for (int w = 0; w < 8; w++) s += wred[tid][w];
            out[b * 5 + tid] = s + bout[tid];
        }
        __syncthreads();
    }
}

extern "C" void kernel_launch(void* const* d_in, const int* in_sizes, int n_in,
                              void* d_out, int out_size)
{
    const float* x    = (const float*)d_in[0];   // (4096, 8, 2048)
    const float* stat = (const float*)d_in[1];   // (5, 2048, 512)
    const float* Wk   = (const float*)d_in[2];   // (1024, 2048)
    const float* bk   = (const float*)d_in[3];
    const float* Wv   = (const float*)d_in[4];
    const float* bv   = (const float*)d_in[5];
    const float* WEk  = (const float*)d_in[6];
    const float* bEk  = (const float*)d_in[7];
    const float* WEv  = (const float*)d_in[8];
    const float* bEv  = (const float*)d_in[9];
    const float* Ww   = (const float*)d_in[10];
    const float* bw   = (const float*)d_in[11];
    const float* Wout = (const float*)d_in[12];  // (5, 2048)
    const float* bout = (const float*)d_in[13];
    float* out = (float*)d_out;                  // (4096, 5, 1)

    float *invE_, *bkv_, *bE2_;
    __half *kvh_, *kn_, *E2_, *Ev_, *simh_, *wh_, *feh_, *xl_, *wtf_, *stT_;
    cudaGetSymbolAddress((void**)&kvh_, g_kvh);
    cudaGetSymbolAddress((void**)&kn_,  g_kn);
    cudaGetSymbolAddress((void**)&E2_,  g_E2);
    cudaGetSymbolAddress((void**)&Ev_,  g_Ev);
    cudaGetSymbolAddress((void**)&simh_, g_simh);
    cudaGetSymbolAddress((void**)&wh_,  g_wh);
    cudaGetSymbolAddress((void**)&feh_, g_feh);
    cudaGetSymbolAddress((void**)&invE_, g_invE);
    cudaGetSymbolAddress((void**)&xl_,  g_xl);
    cudaGetSymbolAddress((void**)&wtf_, g_wtf);
    cudaGetSymbolAddress((void**)&stT_, g_stT);
    cudaGetSymbolAddress((void**)&bkv_, g_bkv);
    cudaGetSymbolAddress((void**)&bE2_, g_bE2);

    constexpr int SMEM = 4 * 2 * 128 * 40 * 2;   // 81920 B (4 stages)
    cudaFuncSetAttribute(gemm_h,    cudaFuncAttributeMaxDynamicSharedMemorySize, SMEM);
    cudaFuncSetAttribute(gemm_dual, cudaFuncAttributeMaxDynamicSharedMemorySize, SMEM);

    // 1. fused preprocessing
    prep_kernel<<<21520, 256>>>(x, Wk, Wv, WEk, WEv, bk, bv, bEk, bEv, stat,
                                (__half2*)xl_, (__half2*)wtf_, bkv_, bE2_, stT_);

    // 2. fused kv + E2 GEMM (832 CTAs, K=2048)
    gemm_dual<<<dim3(16, 52), 256, SMEM>>>(xl_, wtf_, kvh_, bkv_,
                                           stT_, wtf_ + 2L * 1024 * 2048, E2_, bE2_);

    // 3. fused transpose_Ev + ssqE + norm_rows
    post1_kernel<<<9216, 256>>>(E2_, Ev_, invE_, kvh_, kn_);

    // 4. sim = kn @ EkT^T (NT, 4096x512x1024, z=5), fp16 out, ldc=2560
    gemm_h<<<dim3(4, 32, 5), 256, SMEM>>>(kn_, 1024, 0,
                                          E2_, 2048, (long)512 * 2048,
                                          simh_, 5 * 512, 512, 1024, nullptr);

    // 5. softmax
    softmax_kernel<<<4096 * 5, 128>>>(simh_, invE_, wh_);

    // 6. fe = w @ Ev^T (NT, 4096x1024x512, z=5), fp16 out
    gemm_h<<<dim3(8, 32, 5), 256, SMEM>>>(wh_, 5 * 512, 512,
                                          Ev_, 512, (long)1024 * 512,
                                          feh_, 1024, (long)4096 * 1024, 512, nullptr);

    // 7. gate + output
    final_kernel<<<256, 256>>>(kvh_, feh_, Ww, bw, Wout, bout, out);
}

// round 11
// speedup vs baseline: 7.1344x; 1.0929x over previous
#include <cuda_runtime.h>
#include <cuda_fp16.h>
#include <math.h>

// Problem dims (fixed): B=4096, T=8, CH_IN=2048, C=1024, N=512, K=5, EPS=1e-8

__device__ __half g_kvh[4096u * 2048u];          // [k | v] fp16 (GEMM out)
__device__ __half g_kn [4096u * 1024u];          // normalized k, fp16
__device__ __half g_E2 [5u * 512u * 2048u];      // [EkT | EvT] [z][n][j], fp16 (bias added)
__device__ __half g_Ev [5u * 1024u * 512u];      // Ev  [z][c][n], fp16 (from E2 transpose)
__device__ __half g_simh[4096u * 5u * 512u];     // sim fp16
__device__ __half g_wh [4096u * 5u * 512u];      // softmax weights fp16
__device__ __half g_feh[5u * 4096u * 1024u];     // feature_E fp16, [z][b][c]
__device__ float  g_invE[5u * 512u];             // 1/max(||Ek col||, eps)
__device__ __half g_xl [4096u * 2048u];          // x_last fp16
__device__ __half g_wtf[4u * 1024u * 2048u];     // Wk|Wv|WEk|WEv fp16 (contiguous)
__device__ __half g_stT[5u * 512u * 2048u];      // static transposed [z][n][i] fp16
__device__ float  g_bkv[2048u];                  // bk | bv
__device__ float  g_bE2[2048u];                  // bEk | bEv

#define DINLINE __device__ __forceinline__

DINLINE void mma_f16(float* c, const unsigned* a, const unsigned* b) {
    asm volatile(
        "mma.sync.aligned.m16n8k16.row.col.f32.f16.f16.f32 "
        "{%0,%1,%2,%3}, {%4,%5,%6,%7}, {%8,%9}, {%0,%1,%2,%3};"
        : "+f"(c[0]), "+f"(c[1]), "+f"(c[2]), "+f"(c[3])
        : "r"(a[0]), "r"(a[1]), "r"(a[2]), "r"(a[3]),
          "r"(b[0]), "r"(b[1]));
}

DINLINE void ldsm4(unsigned& r0, unsigned& r1, unsigned& r2, unsigned& r3, unsigned saddr) {
    asm volatile("ldmatrix.sync.aligned.m8n8.x4.shared.b16 {%0,%1,%2,%3}, [%4];"
                 : "=r"(r0), "=r"(r1), "=r"(r2), "=r"(r3) : "r"(saddr));
}

DINLINE void cp16(void* dst_smem, const void* src) {
    unsigned d = (unsigned)__cvta_generic_to_shared(dst_smem);
    asm volatile("cp.async.cg.shared.global [%0], [%1], 16;" :: "r"(d), "l"(src));
}
DINLINE void cp_commit() { asm volatile("cp.async.commit_group;"); }
DINLINE void cp_wait2()  { asm volatile("cp.async.wait_group 2;"); }
DINLINE void cp_wait0()  { asm volatile("cp.async.wait_group 0;"); }

// ---------------------------------------------------------------------------
// FP16 NT GEMM body (C = A * B^T), fp32 accumulate. cp.async 4-stage + ldmatrix.
// 128x128x32 CTA tile, 128 threads = 4 warps in a 2x2 grid, warp tile 64x64.
// Per chunk per warp: 16 LDSM feeding 64 independent m16n8k16 MMAs (4:1 ratio)
// -> long MMA chains keep the HMMA pipe busy despite 2 warps/SMSP.
// SMEM rows stride 40 halves (80B) -> ldmatrix conflict-free, cp16-aligned.
// C is __half (bias added in fp32, then rounded).
// ---------------------------------------------------------------------------
DINLINE void gemm_body(const __half* __restrict__ A, long lda,
                       const __half* __restrict__ Bm, long ldb,
                       __half* __restrict__ Cm, long ldc,
                       int Kd, const float* __restrict__ bias_n,
                       int m0, int n0, char* smem)
{
    constexpr int ST = 40;
    constexpr unsigned ABYTES = 128 * ST * 2;  // 10240
    constexpr unsigned STAGE  = 2 * ABYTES;    // 20480

    const unsigned shb = (unsigned)__cvta_generic_to_shared(smem);
    const int tid  = threadIdx.x;
    const int lane = tid & 31;
    const int wid  = tid >> 5;                 // 0..3
    const int g  = lane >> 2;
    const int tg = lane & 3;
    const int m_w = (wid & 1) * 64;
    const int n_w = (wid >> 1) * 64;

    const int rr = lane & 7, q = lane >> 3;
    const int arow = ((q & 1) << 3) + rr;
    const int acol = (q >> 1) << 3;
    const int brow = ((q >> 1) << 3) + rr;
    const int bcol = (q & 1) << 3;

    unsigned aoff[4], boff[4];
#pragma unroll
    for (int mt = 0; mt < 4; mt++)
        aoff[mt] = ((m_w + mt * 16 + arow) * ST + acol) * 2;
#pragma unroll
    for (int nt2 = 0; nt2 < 4; nt2++)
        boff[nt2] = ABYTES + ((n_w + nt2 * 16 + brow) * ST + bcol) * 2;

    float acc[4][8][4];
#pragma unroll
    for (int i = 0; i < 4; i++)
#pragma unroll
        for (int j = 0; j < 8; j++)
#pragma unroll
            for (int p = 0; p < 4; p++) acc[i][j][p] = 0.f;

    auto issue = [&](int t) {
        const int kt = t << 5;
        char* stg = smem + (unsigned)(t & 3) * STAGE;
#pragma unroll
        for (int i = 0; i < 4; i++) {          // A: 128 rows x 4 chunks of 16B
            int lin = i * 128 + tid;
            int r = lin >> 2, c = lin & 3;
            cp16(stg + r * 80 + c * 16, A + (long)(m0 + r) * lda + kt + c * 8);
        }
#pragma unroll
        for (int i = 0; i < 4; i++) {          // B: 128 rows x 4 chunks
            int lin = i * 128 + tid;
            int r = lin >> 2, c = lin & 3;
            cp16(stg + ABYTES + r * 80 + c * 16, Bm + (long)(n0 + r) * ldb + kt + c * 8);
        }
        cp_commit();
    };

    const int KT = Kd >> 5;
    issue(0);
    issue(1);
    issue(2);

    for (int t = 0; t < KT; t++) {
        cp_wait2();
        __syncthreads();
        int tn = t + 3;
        if (tn < KT) issue(tn); else cp_commit();

        const unsigned stb = shb + (unsigned)(t & 3) * STAGE;
#pragma unroll
        for (int s = 0; s < 2; s++) {
            const unsigned kb = s * 32;
            unsigned af[4][4], bf[8][2];
#pragma unroll
            for (int mt = 0; mt < 4; mt++)
                ldsm4(af[mt][0], af[mt][1], af[mt][2], af[mt][3], stb + aoff[mt] + kb);
#pragma unroll
            for (int nt2 = 0; nt2 < 4; nt2++)
                ldsm4(bf[2 * nt2][0], bf[2 * nt2][1],
                      bf[2 * nt2 + 1][0], bf[2 * nt2 + 1][1], stb + boff[nt2] + kb);
#pragma unroll
            for (int mt = 0; mt < 4; mt++)
#pragma unroll
                for (int nt = 0; nt < 8; nt++)
                    mma_f16(acc[mt][nt], af[mt], bf[nt]);
        }
    }
    cp_wait0();

#pragma unroll
    for (int mt = 0; mt < 4; mt++) {
        int r0 = m0 + m_w + mt * 16 + g;
#pragma unroll
        for (int nt = 0; nt < 8; nt++) {
            int cc = n0 + n_w + nt * 8 + 2 * tg;
            float bn0 = bias_n ? bias_n[cc]     : 0.f;
            float bn1 = bias_n ? bias_n[cc + 1] : 0.f;
            const float* c = acc[mt][nt];
            *(__half2*)(Cm + (long)r0 * ldc + cc) =
                __floats2half2_rn(c[0] + bn0, c[1] + bn1);
            *(__half2*)(Cm + (long)(r0 + 8) * ldc + cc) =
                __floats2half2_rn(c[2] + bn0, c[3] + bn1);
        }
    }
}

// Generic batched NT GEMM (used for sim & fe).
__global__ __launch_bounds__(128, 2)
void gemm_h(const __half* __restrict__ A, long lda, long sAz,
            const __half* __restrict__ Bm, long ldb, long sBz,
            __half* __restrict__ Cm, long ldc, long sCz,
            int Kd, const float* __restrict__ bias_n)
{
    extern __shared__ char smem[];
    gemm_body(A + (long)blockIdx.z * sAz, lda,
              Bm + (long)blockIdx.z * sBz, ldb,
              Cm + (long)blockIdx.z * sCz, ldc,
              Kd, bias_n, blockIdx.y * 128, blockIdx.x * 128, smem);
}

// Fused launch: kv GEMM (y<32) + E2 GEMM (y>=32, z=(y-32)/4). K=2048 both.
__global__ __launch_bounds__(128, 2)
void gemm_dual(const __half* __restrict__ xl, const __half* __restrict__ wkv,
               __half* __restrict__ kvh, const float* __restrict__ bkv,
               const __half* __restrict__ stT, const __half* __restrict__ wE,
               __half* __restrict__ E2, const float* __restrict__ bE2)
{
    extern __shared__ char smem[];
    const int y = blockIdx.y;
    if (y < 32) {
        gemm_body(xl, 2048, wkv, 2048, kvh, 2048,
                  2048, bkv, y * 128, blockIdx.x * 128, smem);
    } else {
        int idx = y - 32;
        int z = idx >> 2, my = idx & 3;
        gemm_body(stT + (long)z * 512 * 2048, 2048, wE, 2048,
                  E2 + (long)z * 512 * 2048, 2048,
                  2048, bE2, my * 128, blockIdx.x * 128, smem);
    }
}

// ---------------------------------------------------------------------------
// Fused preprocessing: gather_x | cvt_w | biases | transpose_static.
// ---------------------------------------------------------------------------
__global__ __launch_bounds__(256)
void prep_kernel(const float* __restrict__ x,
                 const float* __restrict__ Wk, const float* __restrict__ Wv,
                 const float* __restrict__ WEk, const float* __restrict__ WEv,
                 const float* __restrict__ bk, const float* __restrict__ bv,
                 const float* __restrict__ bEk, const float* __restrict__ bEv,
                 const float* __restrict__ stat,
                 __half2* __restrict__ xl, __half2* __restrict__ wtf,
                 float* __restrict__ bkv, float* __restrict__ bE2,
                 __half* __restrict__ stT)
{
    __shared__ float tile[32][33];
    const int blk = blockIdx.x, tid = threadIdx.x;

    if (blk < 8192) {                                   // gather_x
        int i = blk * 256 + tid;
        int b  = i >> 9;
        int c4 = (i & 511) * 4;
        float4 v = *(const float4*)(x + (long)b * 16384 + 14336 + c4);
        xl[(long)b * 1024 + (i & 511) * 2]     = __floats2half2_rn(v.x, v.y);
        xl[(long)b * 1024 + (i & 511) * 2 + 1] = __floats2half2_rn(v.z, v.w);
    } else if (blk < 16384) {                           // cvt_w
        int j = (blk - 8192) * 256 + tid;
        int m = j >> 19;
        int i = j & 0x7FFFF;
        const float* src = (m == 0) ? Wk : (m == 1) ? Wv : (m == 2) ? WEk : WEv;
        float4 v = ((const float4*)src)[i];
        __half2* dst = wtf + (long)m * 1048576 + 2 * i;
        dst[0] = __floats2half2_rn(v.x, v.y);
        dst[1] = __floats2half2_rn(v.z, v.w);
    } else if (blk < 16400) {                           // biases
        int i = (blk - 16384) * 256 + tid;              // 0..4095
        if (i < 2048) bkv[i] = (i < 1024) ? bk[i] : bv[i - 1024];
        else {
            int j = i - 2048;
            bE2[j] = (j < 1024) ? bEk[j] : bEv[j - 1024];
        }
    } else {                                            // transpose_static
        int t = blk - 16400;                            // 0..5119
        int z = t >> 10;
        int rem = t & 1023;
        int i0 = (rem & 63) * 32;
        int n0 = (rem >> 6) * 32;
        int tx = tid & 31, ty = tid >> 5;
        const float* src = stat + (long)z * 2048 * 512;
        __half* dst = stT + (long)z * 512 * 2048;
#pragma unroll
        for (int d = 0; d < 4; d++) {
            int row = i0 + ty + d * 8;
            tile[ty + d * 8][tx] = src[(long)row * 512 + n0 + tx];
        }
        __syncthreads();
#pragma unroll
        for (int d = 0; d < 4; d++) {
            int n = n0 + ty + d * 8;
            dst[(long)n * 2048 + i0 + tx] = __float2half_rn(tile[tx][ty + d * 8]);
        }
    }
}

// ---------------------------------------------------------------------------
// Fused post-GEMM1: transpose_Ev | ssqE | norm_rows.
// ---------------------------------------------------------------------------
__global__ __launch_bounds__(256)
void post1_kernel(const __half* __restrict__ E2, __half* __restrict__ Ev,
                  float* __restrict__ invE,
                  const __half* __restrict__ KV, __half* __restrict__ KN)
{
    __shared__ float red[256];
    __shared__ __half htile[32][33];
    const int blk = blockIdx.x, tid = threadIdx.x;

    if (blk < 2560) {                                   // transpose_Ev
        int z = blk >> 9;
        int rem = blk & 511;
        int c0 = (rem >> 4) * 32;
        int n0 = (rem & 15) * 32;
        int tx = tid & 31, ty = tid >> 5;
        const __half* src = E2 + (long)z * 512 * 2048 + 1024;
        __half* dst = Ev + (long)z * 1024 * 512;
#pragma unroll
        for (int d = 0; d < 4; d++) {
            int n = n0 + ty + d * 8;
            htile[ty + d * 8][tx] = src[(long)n * 2048 + c0 + tx];
        }
        __syncthreads();
#pragma unroll
        for (int d = 0; d < 4; d++) {
            int c = c0 + ty + d * 8;
            dst[(long)c * 512 + n0 + tx] = htile[tx][ty + d * 8];
        }
    } else if (blk < 5120) {                            // ssqE
        int row = blk - 2560;
        const __half2* base = (const __half2*)(E2 + (long)row * 2048);
        float2 a = __half22float2(base[tid * 2]);
        float2 b = __half22float2(base[tid * 2 + 1]);
        red[tid] = a.x * a.x + a.y * a.y + b.x * b.x + b.y * b.y;
        __syncthreads();
        for (int st = 128; st > 0; st >>= 1) {
            if (tid < st) red[tid] += red[tid + st];
            __syncthreads();
        }
        if (tid == 0) invE[row] = 1.f / fmaxf(sqrtf(red[0]), 1e-8f);
    } else {                                            // norm_rows
        int b = blk - 5120;
        const __half2* row = (const __half2*)(KV + (long)b * 2048);
        float2 a = __half22float2(row[tid * 2]);
        float2 c = __half22float2(row[tid * 2 + 1]);
        red[tid] = a.x * a.x + a.y * a.y + c.x * c.x + c.y * c.y;
        __syncthreads();
        for (int st = 128; st > 0; st >>= 1) {
            if (tid < st) red[tid] += red[tid + st];
            __syncthreads();
        }
        float inv = 1.f / fmaxf(sqrtf(red[0]), 1e-8f);
        __half2* o = (__half2*)(KN + (long)b * 1024);
        o[tid * 2]     = __floats2half2_rn(a.x * inv, a.y * inv);
        o[tid * 2 + 1] = __floats2half2_rn(c.x * inv, c.y * inv);
    }
}

// scale by invE, softmax over 512, fp16 in / fp16 out. row = b*5+z.
__global__ void softmax_kernel(const __half* __restrict__ S, const float* __restrict__ invE,
                               __half* __restrict__ W)
{
    int row = blockIdx.x;
    int z = row % 5;
    const __half2* base = (const __half2*)(S + (long)row * 512);
    int tid = threadIdx.x;
    float2 a = __half22float2(base[tid * 2]);
    float2 b = __half22float2(base[tid * 2 + 1]);
    float4 v = make_float4(a.x, a.y, b.x, b.y);
    float4 e = *(const float4*)&invE[z * 512 + tid * 4];
    v.x *= e.x; v.y *= e.y; v.z *= e.z; v.w *= e.w;
    __shared__ float sred[128];
    sred[tid] = fmaxf(fmaxf(v.x, v.y), fmaxf(v.z, v.w));
    __syncthreads();
    for (int st = 64; st > 0; st >>= 1) {
        if (tid < st) sred[tid] = fmaxf(sred[tid], sred[tid + st]);
        __syncthreads();
    }
    float m = sred[0];
    __syncthreads();
    v.x = expf(v.x - m); v.y = expf(v.y - m); v.z = expf(v.z - m); v.w = expf(v.w - m);
    sred[tid] = v.x + v.y + v.z + v.w;
    __syncthreads();
    for (int st = 64; st > 0; st >>= 1) {
        if (tid < st) sred[tid] += sred[tid + st];
        __syncthreads();
    }
    float inv = 1.f / sred[0];
    __half2* o = (__half2*)(W + (long)row * 512);
    o[tid * 2]     = __floats2half2_rn(v.x * inv, v.y * inv);
    o[tid * 2 + 1] = __floats2half2_rn(v.z * inv, v.w * inv);
}

// ---------------------------------------------------------------------------
// Final stage: gate + concat + output GEMV. grid = B/16, 256 threads.
// ---------------------------------------------------------------------------
__global__ __launch_bounds__(256)
void final_kernel(const __half* __restrict__ kvh,
                  const __half* __restrict__ feh,
                  const float* __restrict__ Ww,
                  const float* __restrict__ bw,
                  const float* __restrict__ Wout,
                  const float* __restrict__ bout,
                  float* __restrict__ out)
{
    const int tid = threadIdx.x, lane = tid & 31, wid = tid >> 5;
    const int c0 = tid * 4;
    const long sz = (long)4096 * 1024;

    float ww[4];
    float wv[5][4], wf[5][4];
    *(float4*)ww = *(const float4*)&Ww[c0];
#pragma unroll
    for (int kk = 0; kk < 5; kk++) {
        *(float4*)wv[kk] = *(const float4*)&Wout[kk * 2048 + c0];
        *(float4*)wf[kk] = *(const float4*)&Wout[kk * 2048 + 1024 + c0];
    }
    const float bwv = bw[0];

    __shared__ float wred[5][8];
    __shared__ float s_fw[5];

    for (int bi = 0; bi < 16; bi++) {
        const int b = blockIdx.x * 16 + bi;
        const long bc = (long)b * 1024 + c0;

        float fe[5][4];
#pragma unroll
        for (int kk = 0; kk < 5; kk++) {
            __half2 h0 = *(const __half2*)(feh + sz * kk + bc);
            __half2 h1 = *(const __half2*)(feh + sz * kk + bc + 2);
            float2 f0 = __half22float2(h0), f1 = __half22float2(h1);
            fe[kk][0] = f0.x; fe[kk][1] = f0.y; fe[kk][2] = f1.x; fe[kk][3] = f1.y;
        }
        __half2 v0 = *(const __half2*)(kvh + (long)b * 2048 + 1024 + c0);
        __half2 v1 = *(const __half2*)(kvh + (long)b * 2048 + 1024 + c0 + 2);
        float2 vf0 = __half22float2(v0), vf1 = __half22float2(v1);

        float acc[5];
#pragma unroll
        for (int kk = 0; kk < 5; kk++) {
            float s = fe[kk][0] * ww[0] + fe[kk][1] * ww[1]
                    + fe[kk][2] * ww[2] + fe[kk][3] * ww[3];
#pragma unroll
            for (int o = 16; o > 0; o >>= 1) s += __shfl_xor_sync(0xFFFFFFFFu, s, o);
            acc[kk] = s;
        }
        if (lane == 0) {
#pragma unroll
            for (int kk = 0; kk < 5; kk++) wred[kk][wid] = acc[kk];
        }
        __syncthreads();
        if (tid < 5) {
            float s = 0.f;
#pragma unroll
            for (int w = 0; w < 8; w++) s += wred[tid][w];
            s_fw[tid] = 1.f / (1.f + expf(-(s + bwv)));
        }
        __syncthreads();
        float fwl[5];
#pragma unroll
        for (int kk = 0; kk < 5; kk++) fwl[kk] = s_fw[kk];

        float fE[4];
#pragma unroll
        for (int qq = 0; qq < 4; qq++) {
            float s = 0.f;
#pragma unroll
            for (int kk = 0; kk < 5; kk++) s = fmaf(fe[kk][qq], fwl[kk], s);
            fE[qq] = fmaxf(s, 0.f);
        }
        float hv[4] = {fmaxf(vf0.x, 0.f), fmaxf(vf0.y, 0.f),
                       fmaxf(vf1.x, 0.f), fmaxf(vf1.y, 0.f)};

        float oacc[5];
#pragma unroll
        for (int kk = 0; kk < 5; kk++) {
            float s = hv[0] * wv[kk][0] + hv[1] * wv[kk][1]
                    + hv[2] * wv[kk][2] + hv[3] * wv[kk][3]
                    + fE[0] * wf[kk][0] + fE[1] * wf[kk][1]
                    + fE[2] * wf[kk][2] + fE[3] * wf[kk][3];
#pragma unroll
            for (int o = 16; o > 0; o >>= 1) s += __shfl_xor_sync(0xFFFFFFFFu, s, o);
            oacc[kk] = s;
        }
        if (lane == 0) {
#pragma unroll
            for (int kk = 0; kk < 5; kk++) wred[kk][wid] = oacc[kk];
        }
        __syncthreads();
        if (tid < 5) {
            float s = 0.f;
#pragma unroll
            for (int w = 0; w < 8; w++) s += wred[tid][w];
            out[b * 5 + tid] = s + bout[tid];
        }
        __syncthreads();
    }
}

extern "C" void kernel_launch(void* const* d_in, const int* in_sizes, int n_in,
                              void* d_out, int out_size)
{
    const float* x    = (const float*)d_in[0];   // (4096, 8, 2048)
    const float* stat = (const float*)d_in[1];   // (5, 2048, 512)
    const float* Wk   = (const float*)d_in[2];   // (1024, 2048)
    const float* bk   = (const float*)d_in[3];
    const float* Wv   = (const float*)d_in[4];
    const float* bv   = (const float*)d_in[5];
    const float* WEk  = (const float*)d_in[6];
    const float* bEk  = (const float*)d_in[7];
    const float* WEv  = (const float*)d_in[8];
    const float* bEv  = (const float*)d_in[9];
    const float* Ww   = (const float*)d_in[10];
    const float* bw   = (const float*)d_in[11];
    const float* Wout = (const float*)d_in[12];  // (5, 2048)
    const float* bout = (const float*)d_in[13];
    float* out = (float*)d_out;                  // (4096, 5, 1)

    float *invE_, *bkv_, *bE2_;
    __half *kvh_, *kn_, *E2_, *Ev_, *simh_, *wh_, *feh_, *xl_, *wtf_, *stT_;
    cudaGetSymbolAddress((void**)&kvh_, g_kvh);
    cudaGetSymbolAddress((void**)&kn_,  g_kn);
    cudaGetSymbolAddress((void**)&E2_,  g_E2);
    cudaGetSymbolAddress((void**)&Ev_,  g_Ev);
    cudaGetSymbolAddress((void**)&simh_, g_simh);
    cudaGetSymbolAddress((void**)&wh_,  g_wh);
    cudaGetSymbolAddress((void**)&feh_, g_feh);
    cudaGetSymbolAddress((void**)&invE_, g_invE);
    cudaGetSymbolAddress((void**)&xl_,  g_xl);
    cudaGetSymbolAddress((void**)&wtf_, g_wtf);
    cudaGetSymbolAddress((void**)&stT_, g_stT);
    cudaGetSymbolAddress((void**)&bkv_, g_bkv);
    cudaGetSymbolAddress((void**)&bE2_, g_bE2);

    constexpr int SMEM = 4 * 2 * 128 * 40 * 2;   // 81920 B (4 stages)
    cudaFuncSetAttribute(gemm_h,    cudaFuncAttributeMaxDynamicSharedMemorySize, SMEM);
    cudaFuncSetAttribute(gemm_dual, cudaFuncAttributeMaxDynamicSharedMemorySize, SMEM);

    // 1. fused preprocessing
    prep_kernel<<<21520, 256>>>(x, Wk, Wv, WEk, WEv, bk, bv, bEk, bEv, stat,
                                (__half2*)xl_, (__half2*)wtf_, bkv_, bE2_, stT_);

    // 2. fused kv + E2 GEMM (832 CTAs, K=2048)
    gemm_dual<<<dim3(16, 52), 128, SMEM>>>(xl_, wtf_, kvh_, bkv_,
                                           stT_, wtf_ + 2L * 1024 * 2048, E2_, bE2_);

    // 3. fused transpose_Ev + ssqE + norm_rows
    post1_kernel<<<9216, 256>>>(E2_, Ev_, invE_, kvh_, kn_);

    // 4. sim = kn @ EkT^T (NT, 4096x512x1024, z=5), fp16 out, ldc=2560
    gemm_h<<<dim3(4, 32, 5), 128, SMEM>>>(kn_, 1024, 0,
                                          E2_, 2048, (long)512 * 2048,
                                          simh_, 5 * 512, 512, 1024, nullptr);

    // 5. softmax
    softmax_kernel<<<4096 * 5, 128>>>(simh_, invE_, wh_);

    // 6. fe = w @ Ev^T (NT, 4096x1024x512, z=5), fp16 out
    gemm_h<<<dim3(8, 32, 5), 128, SMEM>>>(wh_, 5 * 512, 512,
                                          Ev_, 512, (long)1024 * 512,
                                          feh_, 1024, (long)4096 * 1024, 512, nullptr);

    // 7. gate + output
    final_kernel<<<256, 256>>>(kvh_, feh_, Ww, bw, Wout, bout, out);
}